// round 4
// baseline (speedup 1.0000x reference)
#include <cuda_runtime.h>

#define BB 128
#define UU 8
#define CC 2048
#define JJ 32
#define SS 16
#define NITER 3

#define JS   (JJ*SS)     // 512
#define SU   (SS*UU)     // 128
#define JSU  (JJ*SS*UU)  // 4096
#define UC   (UU*CC)     // 16384
#define CB   (CC*BB)
#define NCHUNK 32        // 32 chunks of 64 c

typedef unsigned long long ull;

// ---------------- packed f32x2 helpers ---------------------------------------
__device__ __forceinline__ ull pk2(float lo, float hi) {
    ull r; asm("mov.b64 %0, {%1, %2};" : "=l"(r) : "f"(lo), "f"(hi)); return r;
}
__device__ __forceinline__ void fma2(ull& d, ull a, ull b) {
    asm("fma.rn.f32x2 %0, %1, %2, %0;" : "+l"(d) : "l"(a), "l"(b));
}
__device__ __forceinline__ void add2(ull& d, ull a) {
    asm("add.rn.f32x2 %0, %0, %1;" : "+l"(d) : "l"(a));
}
__device__ __forceinline__ void upk2(float& lo, float& hi, ull v) {
    asm("mov.b64 {%0, %1}, %2;" : "=f"(lo), "=f"(hi) : "l"(v));
}

// ---------------- device scratch ----------------------------------------------
__device__ float g_xT[UU*CC*BB];       // [u][c][b]  8 MB
__device__ float g_Wr[CC*JSU];         // [c][j][u][s] 33.5 MB
__device__ float g_b[JJ*CC];           // logits [j][c]
__device__ float g_c[JJ*CC];           // coeffs [j][c]
__device__ float g_sp[NCHUNK*BB*JS];   // partial s, 8 MB
__device__ float g_M[UC*JS];           // M[(u,c)][(j,s)] 33.5 MB

// ---------------- transpose x -> xT[u][c][b] -----------------------------------
__global__ void transpose_x_k(const float* __restrict__ x) {
    __shared__ float tile[32][33];
    int u  = blockIdx.z;
    int c0 = blockIdx.x * 32;
    int b0 = blockIdx.y * 32;
    int tx = threadIdx.x, ty = threadIdx.y;
    tile[ty][tx] = x[(size_t)(b0 + ty) * (UU*CC) + (size_t)u * CC + c0 + tx];
    __syncthreads();
    g_xT[(size_t)u * CB + (size_t)(c0 + ty) * BB + b0 + tx] = tile[tx][ty];
}

// ---------------- reorder W[c][j][s][u] -> Wr[c][j][u][s] -----------------------
__global__ void reorder_w_k(const float* __restrict__ Wg) {
    int row = blockIdx.x * 2 + (threadIdx.x >> 7);  // c*J + j
    int t   = threadIdx.x & 127;                    // u*16+s
    int u = t >> 4, s = t & 15;
    g_Wr[(size_t)row * SU + t] = Wg[(size_t)row * SU + s * UU + u];
}

// ---------------- init: b=0, c=1/2048 (softmax of zeros) ------------------------
__global__ void init_k() {
    int i = blockIdx.x * blockDim.x + threadIdx.x;
    if (i < JJ*CC) { g_b[i] = 0.0f; g_c[i] = 1.0f / 2048.0f; }
}

// ---------------- softmax over c for each j (coalesced) -------------------------
__global__ void softmax_k() {
    int j = blockIdx.x;       // 32
    int t = threadIdx.x;      // 512
    __shared__ float redm[16];
    __shared__ float reds[16];
    const float4* bp = (const float4*)(g_b + (size_t)j * CC);
    float4 v = bp[t];
    float mx = fmaxf(fmaxf(v.x, v.y), fmaxf(v.z, v.w));
    #pragma unroll
    for (int o = 16; o > 0; o >>= 1) mx = fmaxf(mx, __shfl_xor_sync(0xffffffffu, mx, o));
    if ((t & 31) == 0) redm[t >> 5] = mx;
    __syncthreads();
    float bmax = redm[0];
    #pragma unroll
    for (int i = 1; i < 16; i++) bmax = fmaxf(bmax, redm[i]);
    float4 e;
    e.x = __expf(v.x - bmax); e.y = __expf(v.y - bmax);
    e.z = __expf(v.z - bmax); e.w = __expf(v.w - bmax);
    float sm = e.x + e.y + e.z + e.w;
    #pragma unroll
    for (int o = 16; o > 0; o >>= 1) sm += __shfl_xor_sync(0xffffffffu, sm, o);
    if ((t & 31) == 0) reds[t >> 5] = sm;
    __syncthreads();
    float tot = 0.0f;
    #pragma unroll
    for (int i = 0; i < 16; i++) tot += reds[i];
    float inv = 1.0f / tot;
    e.x *= inv; e.y *= inv; e.z *= inv; e.w *= inv;
    ((float4*)(g_c + (size_t)j * CC))[t] = e;
}

// ---------------- fused s-pass ---------------------------------------------------
// s[b,j,s] = sum_c coef[j,c] * sum_u Wr[c,j,u,s] * xT[u,c,b]
// block = (j, chunk of 64 c). 128 thr. Two stages of 32 c (16 KB smem each,
// aliased with the reduction buffer). Lane owns b = lane*4 + {0..3} (LDG.128).
// Warp w handles 8 c per stage. 2-region tree reduce at the end.
__global__ void __launch_bounds__(128, 5) s_pass_k() {
    int j     = blockIdx.x;   // 32
    int chunk = blockIdx.y;   // 32
    int t     = threadIdx.x;
    int w = t >> 5, lane = t & 31;
    int cbase = chunk * 64;

    __shared__ __align__(16) float wsm[32 * 128];  // 16 KB (stage OR reduce buffer)

    ull acc[4][8];
    #pragma unroll
    for (int bi = 0; bi < 4; bi++)
        #pragma unroll
        for (int sp = 0; sp < 8; sp++) acc[bi][sp] = 0ULL;

    const float* xb = g_xT + lane * 4;

    for (int st = 0; st < 2; st++) {
        int sbase = cbase + st * 32;
        __syncthreads();
        // stage coef-scaled W: 32 c x 32 float4
        {
            const float4* Wr4 = (const float4*)g_Wr;
            float4* w4 = (float4*)wsm;
            #pragma unroll
            for (int i = 0; i < 8; i++) {
                int lin = i * 128 + t;          // 0..1023
                int cl = lin >> 5, q = lin & 31;
                float coef = __ldg(&g_c[(size_t)j * CC + sbase + cl]);
                float4 wv = Wr4[(size_t)(sbase + cl) * (JSU/4) + j * 32 + q];
                wv.x *= coef; wv.y *= coef; wv.z *= coef; wv.w *= coef;
                w4[cl * 32 + q] = wv;
            }
        }
        __syncthreads();

        #pragma unroll 1
        for (int k = 0; k < 8; k++) {
            int cl = w * 8 + k;
            int c  = sbase + cl;
            #pragma unroll
            for (int u = 0; u < UU; u++) {
                float4 xv = *(const float4*)(xb + (size_t)u * CB + (size_t)c * BB);
                ull xd0 = pk2(xv.x, xv.x), xd1 = pk2(xv.y, xv.y);
                ull xd2 = pk2(xv.z, xv.z), xd3 = pk2(xv.w, xv.w);
                const ulonglong2* w2 = (const ulonglong2*)&wsm[cl * 128 + u * 16];
                ulonglong2 wv0 = w2[0], wv1 = w2[1], wv2 = w2[2], wv3 = w2[3];
                fma2(acc[0][0], wv0.x, xd0); fma2(acc[1][0], wv0.x, xd1);
                fma2(acc[2][0], wv0.x, xd2); fma2(acc[3][0], wv0.x, xd3);
                fma2(acc[0][1], wv0.y, xd0); fma2(acc[1][1], wv0.y, xd1);
                fma2(acc[2][1], wv0.y, xd2); fma2(acc[3][1], wv0.y, xd3);
                fma2(acc[0][2], wv1.x, xd0); fma2(acc[1][2], wv1.x, xd1);
                fma2(acc[2][2], wv1.x, xd2); fma2(acc[3][2], wv1.x, xd3);
                fma2(acc[0][3], wv1.y, xd0); fma2(acc[1][3], wv1.y, xd1);
                fma2(acc[2][3], wv1.y, xd2); fma2(acc[3][3], wv1.y, xd3);
                fma2(acc[0][4], wv2.x, xd0); fma2(acc[1][4], wv2.x, xd1);
                fma2(acc[2][4], wv2.x, xd2); fma2(acc[3][4], wv2.x, xd3);
                fma2(acc[0][5], wv2.y, xd0); fma2(acc[1][5], wv2.y, xd1);
                fma2(acc[2][5], wv2.y, xd2); fma2(acc[3][5], wv2.y, xd3);
                fma2(acc[0][6], wv3.x, xd0); fma2(acc[1][6], wv3.x, xd1);
                fma2(acc[2][6], wv3.x, xd2); fma2(acc[3][6], wv3.x, xd3);
                fma2(acc[0][7], wv3.y, xd0); fma2(acc[1][7], wv3.y, xd1);
                fma2(acc[2][7], wv3.y, xd2); fma2(acc[3][7], wv3.y, xd3);
            }
        }
    }

    // 2-region tree reduce: region r = warp r + warp r+2 ; b index = lane*4+bi
    __syncthreads();
    ull* redU = (ull*)wsm;   // 2048 ULL = 16 KB
    if (w >= 2) {
        #pragma unroll
        for (int bi = 0; bi < 4; bi++)
            #pragma unroll
            for (int sp = 0; sp < 8; sp++)
                redU[(w - 2) * 1024 + sp * 128 + lane * 4 + bi] = acc[bi][sp];
    }
    __syncthreads();
    if (w < 2) {
        #pragma unroll
        for (int bi = 0; bi < 4; bi++)
            #pragma unroll
            for (int sp = 0; sp < 8; sp++) {
                int idx = w * 1024 + sp * 128 + lane * 4 + bi;
                ull s = redU[idx];
                add2(s, acc[bi][sp]);
                redU[idx] = s;
            }
    }
    __syncthreads();

    // thread t owns b = t: sum region0 + region1
    float res[16];
    #pragma unroll
    for (int sp = 0; sp < 8; sp++) {
        ull s = redU[sp * 128 + t];
        add2(s, redU[1024 + sp * 128 + t]);
        upk2(res[2*sp], res[2*sp+1], s);
    }
    float4* dst = (float4*)&g_sp[(size_t)chunk * (BB*JS) + (size_t)t * JS + j * SS];
    #pragma unroll
    for (int q = 0; q < 4; q++)
        dst[q] = make_float4(res[q*4], res[q*4+1], res[q*4+2], res[q*4+3]);
}

// ---------------- reduce partials + squash -> v ---------------------------------
__global__ void squash_k(float* __restrict__ out) {
    int b = blockIdx.x;      // 128
    int t = threadIdx.x;     // 512
    float sv = 0.0f;
    #pragma unroll 8
    for (int k = 0; k < NCHUNK; k++)
        sv += g_sp[(size_t)k * (BB*JS) + (size_t)b * JS + t];

    __shared__ float sq[512];
    __shared__ float msqs[SS];
    sq[t] = sv * sv;
    __syncthreads();
    if (t < SS) {
        float m = 0.0f;
        #pragma unroll
        for (int jj = 0; jj < JJ; jj++) m += sq[jj * SS + t];
        msqs[t] = m;
    }
    __syncthreads();
    float msq = msqs[t & (SS - 1)];
    float scale = msq / ((1.0f + msq) * sqrtf(msq));
    out[(size_t)b * JS + t] = sv * scale;
}

// ---------------- M = xT(16384x128) * v(128x512) --------------------------------
// 128x128 tile, 512 threads, 4 rows x 8 cols per thread (acc = 16 ULL).
#define PADA 132
__global__ void __launch_bounds__(512, 2) mgemm_k(const float* __restrict__ v) {
    __shared__ __align__(16) float As[32 * PADA];  // [kk][r]
    __shared__ __align__(16) float Bs[32 * 128];   // [kk][cc]
    int col0 = blockIdx.x * 128;   // 4
    int row0 = blockIdx.y * 128;   // 128
    int t  = threadIdx.x;
    int tr = t >> 4;               // 0..31 -> rows tr*4..+4
    int tc = t & 15;               // 0..15 -> cols tc*8..+8

    ull acc[4][4];
    #pragma unroll
    for (int i = 0; i < 4; i++)
        #pragma unroll
        for (int q = 0; q < 4; q++) acc[i][q] = 0ULL;

    for (int k0 = 0; k0 < BB; k0 += 32) {
        // stage A (transposed to [kk][r]) : 1024 float4, 2 per thread
        #pragma unroll
        for (int i = 0; i < 2; i++) {
            int lin = i * 512 + t;
            int r = lin >> 3, kq = lin & 7;
            float4 a = *(const float4*)&g_xT[(size_t)(row0 + r) * BB + k0 + kq * 4];
            As[(kq*4+0) * PADA + r] = a.x;
            As[(kq*4+1) * PADA + r] = a.y;
            As[(kq*4+2) * PADA + r] = a.z;
            As[(kq*4+3) * PADA + r] = a.w;
        }
        // stage B: 1024 float4, 2 per thread
        #pragma unroll
        for (int i = 0; i < 2; i++) {
            int lin = i * 512 + t;
            int kk = lin >> 5, cq = lin & 31;
            ((float4*)Bs)[kk * 32 + cq] =
                *(const float4*)&v[(size_t)(k0 + kk) * JS + col0 + cq * 4];
        }
        __syncthreads();
        #pragma unroll 8
        for (int kk = 0; kk < 32; kk++) {
            float4 a = *(const float4*)&As[kk * PADA + tr * 4];
            const ulonglong2* bp = (const ulonglong2*)&Bs[kk * 128 + tc * 8];
            ulonglong2 b0 = bp[0], b1 = bp[1];
            ull a0 = pk2(a.x, a.x), a1 = pk2(a.y, a.y);
            ull a2 = pk2(a.z, a.z), a3 = pk2(a.w, a.w);
            fma2(acc[0][0], b0.x, a0); fma2(acc[0][1], b0.y, a0);
            fma2(acc[0][2], b1.x, a0); fma2(acc[0][3], b1.y, a0);
            fma2(acc[1][0], b0.x, a1); fma2(acc[1][1], b0.y, a1);
            fma2(acc[1][2], b1.x, a1); fma2(acc[1][3], b1.y, a1);
            fma2(acc[2][0], b0.x, a2); fma2(acc[2][1], b0.y, a2);
            fma2(acc[2][2], b1.x, a2); fma2(acc[2][3], b1.y, a2);
            fma2(acc[3][0], b0.x, a3); fma2(acc[3][1], b0.y, a3);
            fma2(acc[3][2], b1.x, a3); fma2(acc[3][3], b1.y, a3);
        }
        __syncthreads();
    }
    #pragma unroll
    for (int ri = 0; ri < 4; ri++) {
        float r[8];
        #pragma unroll
        for (int q = 0; q < 4; q++) upk2(r[2*q], r[2*q+1], acc[ri][q]);
        float4* dst = (float4*)&g_M[(size_t)(row0 + tr*4 + ri) * JS + col0 + tc * 8];
        dst[0] = make_float4(r[0], r[1], r[2], r[3]);
        dst[1] = make_float4(r[4], r[5], r[6], r[7]);
    }
}

// ---------------- b[j,c] += (1/B) sum_{u,s} Wr[c,j,u,s]*M[(u,c),(j,s)] ----------
__global__ void __launch_bounds__(256) bupdate_k() {
    int j = blockIdx.x;                      // 32
    int c = blockIdx.y * 256 + threadIdx.x;  // 8 x 256
    const float4* wr4 = (const float4*)(g_Wr + (size_t)c * JSU + (size_t)j * SU);
    float acc = 0.0f;
    #pragma unroll
    for (int u = 0; u < UU; u++) {
        const float4* m4 = (const float4*)&g_M[((size_t)u * CC + c) * JS + j * SS];
        #pragma unroll
        for (int q = 0; q < 4; q++) {
            float4 wv = wr4[u * 4 + q];
            float4 m  = m4[q];
            acc += wv.x*m.x + wv.y*m.y + wv.z*m.z + wv.w*m.w;
        }
    }
    g_b[(size_t)j * CC + c] += acc * (1.0f / (float)BB);
}

// ---------------- launcher --------------------------------------------------------
extern "C" void kernel_launch(void* const* d_in, const int* in_sizes, int n_in,
                              void* d_out, int out_size) {
    const float* x = (const float*)d_in[0];   // [B,U,C]
    const float* W = (const float*)d_in[1];   // [1,C,J,S,U]
    float* out = (float*)d_out;               // [B,J,S,1]

    transpose_x_k<<<dim3(CC/32, BB/32, UU), dim3(32, 32)>>>(x);
    reorder_w_k<<<CC*JJ/2, 256>>>(W);
    init_k<<<(JJ*CC + 255)/256, 256>>>();

    for (int it = 0; it < NITER; it++) {
        if (it > 0) softmax_k<<<JJ, 512>>>();   // iter 0: uniform coeffs from init
        s_pass_k<<<dim3(JJ, NCHUNK), 128>>>();
        squash_k<<<BB, 512>>>(out);
        if (it < NITER - 1) {
            mgemm_k<<<dim3(JS/128, UC/128), 512>>>(out);
            bupdate_k<<<dim3(JJ, CC/256), 256>>>();
        }
    }
}

// round 5
// speedup vs baseline: 1.2666x; 1.2666x over previous
#include <cuda_runtime.h>

#define BB 128
#define UU 8
#define CC 2048
#define JJ 32
#define SS 16
#define NITER 3

#define JS   (JJ*SS)     // 512
#define SU   (SS*UU)     // 128
#define JSU  (JJ*SS*UU)  // 4096
#define UC   (UU*CC)     // 16384
#define CB   (CC*BB)     // 262144
#define NCHUNK 64        // 64 chunks of 32 c

typedef unsigned long long ull;

// ---------------- packed f32x2 helpers ---------------------------------------
__device__ __forceinline__ ull pk2(float lo, float hi) {
    ull r; asm("mov.b64 %0, {%1, %2};" : "=l"(r) : "f"(lo), "f"(hi)); return r;
}
__device__ __forceinline__ void fma2(ull& d, ull a, ull b) {
    asm("fma.rn.f32x2 %0, %1, %2, %0;" : "+l"(d) : "l"(a), "l"(b));
}
__device__ __forceinline__ void add2(ull& d, ull a) {
    asm("add.rn.f32x2 %0, %0, %1;" : "+l"(d) : "l"(a));
}
__device__ __forceinline__ void upk2(float& lo, float& hi, ull v) {
    asm("mov.b64 {%0, %1}, %2;" : "=f"(lo), "=f"(hi) : "l"(v));
}

// ---------------- device scratch ----------------------------------------------
__device__ float g_xT[UU*CC*BB];       // [u][c][b]  8 MB
__device__ float g_Wr[CC*JSU];         // [c][j][u][s] 33.5 MB
__device__ float g_b[JJ*CC];           // logits [j][c]
__device__ float g_c[JJ*CC];           // coeffs [j][c]
__device__ float g_sp[NCHUNK*BB*JS];   // partial s, 16 MB
__device__ float g_bp[UU*CC*JJ];       // per-u partial b-updates, 2 MB

// ---------------- transpose x -> xT[u][c][b] -----------------------------------
__global__ void transpose_x_k(const float* __restrict__ x) {
    __shared__ float tile[32][33];
    int u  = blockIdx.z;
    int c0 = blockIdx.x * 32;
    int b0 = blockIdx.y * 32;
    int tx = threadIdx.x, ty = threadIdx.y;
    tile[ty][tx] = x[(size_t)(b0 + ty) * (UU*CC) + (size_t)u * CC + c0 + tx];
    __syncthreads();
    g_xT[(size_t)u * CB + (size_t)(c0 + ty) * BB + b0 + tx] = tile[tx][ty];
}

// ---------------- reorder W[c][j][s][u] -> Wr[c][j][u][s] -----------------------
__global__ void reorder_w_k(const float* __restrict__ Wg) {
    int row = blockIdx.x * 2 + (threadIdx.x >> 7);  // c*J + j
    int t   = threadIdx.x & 127;                    // u*16+s
    int u = t >> 4, s = t & 15;
    g_Wr[(size_t)row * SU + t] = Wg[(size_t)row * SU + s * UU + u];
}

// ---------------- init: b=0, c=1/2048 (softmax of zeros) ------------------------
__global__ void init_k() {
    int i = blockIdx.x * blockDim.x + threadIdx.x;
    if (i < JJ*CC) { g_b[i] = 0.0f; g_c[i] = 1.0f / 2048.0f; }
}

// ---------------- softmax over c for each j (coalesced) -------------------------
__global__ void softmax_k() {
    int j = blockIdx.x;       // 32
    int t = threadIdx.x;      // 512
    __shared__ float redm[16];
    __shared__ float reds[16];
    const float4* bp = (const float4*)(g_b + (size_t)j * CC);
    float4 v = bp[t];
    float mx = fmaxf(fmaxf(v.x, v.y), fmaxf(v.z, v.w));
    #pragma unroll
    for (int o = 16; o > 0; o >>= 1) mx = fmaxf(mx, __shfl_xor_sync(0xffffffffu, mx, o));
    if ((t & 31) == 0) redm[t >> 5] = mx;
    __syncthreads();
    float bmax = redm[0];
    #pragma unroll
    for (int i = 1; i < 16; i++) bmax = fmaxf(bmax, redm[i]);
    float4 e;
    e.x = __expf(v.x - bmax); e.y = __expf(v.y - bmax);
    e.z = __expf(v.z - bmax); e.w = __expf(v.w - bmax);
    float sm = e.x + e.y + e.z + e.w;
    #pragma unroll
    for (int o = 16; o > 0; o >>= 1) sm += __shfl_xor_sync(0xffffffffu, sm, o);
    if ((t & 31) == 0) reds[t >> 5] = sm;
    __syncthreads();
    float tot = 0.0f;
    #pragma unroll
    for (int i = 0; i < 16; i++) tot += reds[i];
    float inv = 1.0f / tot;
    e.x *= inv; e.y *= inv; e.z *= inv; e.w *= inv;
    ((float4*)(g_c + (size_t)j * CC))[t] = e;
}

// ---------------- fused s-pass ---------------------------------------------------
// s[b,j,s] = sum_c coef[j,c] * sum_u Wr[c,j,u,s] * xT[u,c,b]
// block = (j, chunk of 32 c), 256 threads = 8 warps.
// warp w: c-group g=w>>1 (8 c), b-half h=w&1. Thread owns b = h*32+lane, +64.
// acc = 2b x 16s = 16 ULL. Conflict-free 2-round reduce over 4 c-groups.
__global__ void __launch_bounds__(256, 4) s_pass_k() {
    int j     = blockIdx.x;   // 32
    int chunk = blockIdx.y;   // 64
    int t     = threadIdx.x;
    int w = t >> 5, lane = t & 31;
    int g = w >> 1, h = w & 1;
    int cbase = chunk * 32;

    __shared__ __align__(16) float wsm[32 * 128];  // 16 KB (stage, then reduce)

    // stage coef-scaled W: 32 c x 32 float4 = 1024 float4, 4 per thread
    {
        const float4* Wr4 = (const float4*)g_Wr;
        float4* w4 = (float4*)wsm;
        #pragma unroll
        for (int i = 0; i < 4; i++) {
            int lin = i * 256 + t;          // 0..1023
            int cl = lin >> 5, q = lin & 31;
            float coef = __ldg(&g_c[j * CC + cbase + cl]);
            float4 wv = Wr4[(size_t)(cbase + cl) * (JSU/4) + j * 32 + q];
            wv.x *= coef; wv.y *= coef; wv.z *= coef; wv.w *= coef;
            w4[cl * 32 + q] = wv;
        }
    }
    __syncthreads();

    ull acc[2][8];
    #pragma unroll
    for (int bi = 0; bi < 2; bi++)
        #pragma unroll
        for (int sp = 0; sp < 8; sp++) acc[bi][sp] = 0ULL;

    int boff = h * 32 + lane;

    #pragma unroll 1
    for (int k = 0; k < 8; k++) {
        int cl = g * 8 + k;
        int c  = cbase + cl;
        #pragma unroll
        for (int u = 0; u < UU; u++) {
            const float* xp = g_xT + u * CB + c * BB + boff;
            float x0 = __ldg(xp);
            float x1 = __ldg(xp + 64);
            ull xd0 = pk2(x0, x0), xd1 = pk2(x1, x1);
            const ulonglong2* w2 = (const ulonglong2*)&wsm[cl * 128 + u * 16];
            ulonglong2 wv0 = w2[0], wv1 = w2[1], wv2 = w2[2], wv3 = w2[3];
            fma2(acc[0][0], wv0.x, xd0); fma2(acc[1][0], wv0.x, xd1);
            fma2(acc[0][1], wv0.y, xd0); fma2(acc[1][1], wv0.y, xd1);
            fma2(acc[0][2], wv1.x, xd0); fma2(acc[1][2], wv1.x, xd1);
            fma2(acc[0][3], wv1.y, xd0); fma2(acc[1][3], wv1.y, xd1);
            fma2(acc[0][4], wv2.x, xd0); fma2(acc[1][4], wv2.x, xd1);
            fma2(acc[0][5], wv2.y, xd0); fma2(acc[1][5], wv2.y, xd1);
            fma2(acc[0][6], wv3.x, xd0); fma2(acc[1][6], wv3.x, xd1);
            fma2(acc[0][7], wv3.y, xd0); fma2(acc[1][7], wv3.y, xd1);
        }
    }

    // reduce over 4 c-groups. regions 0,1 in 16 KB; stride-1 lanes (no conflicts)
    __syncthreads();
    ull* redU = (ull*)wsm;   // 2048 ULL
    if (g < 2) {
        #pragma unroll
        for (int bi = 0; bi < 2; bi++)
            #pragma unroll
            for (int sp = 0; sp < 8; sp++)
                redU[g * 1024 + sp * 128 + boff + bi * 64] = acc[bi][sp];
    }
    __syncthreads();
    if (g >= 2) {
        #pragma unroll
        for (int bi = 0; bi < 2; bi++)
            #pragma unroll
            for (int sp = 0; sp < 8; sp++) {
                int idx = (g - 2) * 1024 + sp * 128 + boff + bi * 64;
                ull s = redU[idx];
                add2(s, acc[bi][sp]);
                redU[idx] = s;
            }
    }
    __syncthreads();

    // threads 0..127: b = t, sum region0 + region1, store 16 floats
    if (t < 128) {
        float res[16];
        #pragma unroll
        for (int sp = 0; sp < 8; sp++) {
            ull s = redU[sp * 128 + t];
            add2(s, redU[1024 + sp * 128 + t]);
            upk2(res[2*sp], res[2*sp+1], s);
        }
        float4* dst = (float4*)&g_sp[(size_t)chunk * (BB*JS) + t * JS + j * SS];
        #pragma unroll
        for (int q = 0; q < 4; q++)
            dst[q] = make_float4(res[q*4], res[q*4+1], res[q*4+2], res[q*4+3]);
    }
}

// ---------------- reduce partials + squash -> v ---------------------------------
__global__ void squash_k(float* __restrict__ out) {
    int b = blockIdx.x;      // 128
    int t = threadIdx.x;     // 512
    float sv = 0.0f;
    #pragma unroll 8
    for (int k = 0; k < NCHUNK; k++)
        sv += g_sp[(size_t)k * (BB*JS) + b * JS + t];

    __shared__ float sq[512];
    __shared__ float msqs[SS];
    sq[t] = sv * sv;
    __syncthreads();
    if (t < SS) {
        float m = 0.0f;
        #pragma unroll
        for (int jj = 0; jj < JJ; jj++) m += sq[jj * SS + t];
        msqs[t] = m;
    }
    __syncthreads();
    float msq = msqs[t & (SS - 1)];
    float scale = msq / ((1.0f + msq) * sqrtf(msq));
    out[b * JS + t] = sv * scale;
}

// ---------------- fused M-GEMM + b-update epilogue ------------------------------
// M = xT(16384x128) * v(128x512); instead of storing M, each thread dots its
// 4x8 acc tile with Wr and emits per-u partial b-updates to g_bp[u][c][j].
#define PADA 132
__global__ void __launch_bounds__(512, 2) mgemm_k(const float* __restrict__ v) {
    __shared__ __align__(16) float As[32 * PADA];  // [kk][r]
    __shared__ __align__(16) float Bs[32 * 128];   // [kk][cc]
    int col0 = blockIdx.x * 128;   // 4
    int row0 = blockIdx.y * 128;   // 128 (spans one u: 128 consecutive c)
    int t  = threadIdx.x;
    int tr = t >> 4;               // 0..31 -> rows tr*4..+4
    int tc = t & 15;               // 0..15 -> cols tc*8..+8

    ull acc[4][4];
    #pragma unroll
    for (int i = 0; i < 4; i++)
        #pragma unroll
        for (int q = 0; q < 4; q++) acc[i][q] = 0ULL;

    for (int k0 = 0; k0 < BB; k0 += 32) {
        #pragma unroll
        for (int i = 0; i < 2; i++) {
            int lin = i * 512 + t;
            int r = lin >> 3, kq = lin & 7;
            float4 a = *(const float4*)&g_xT[(size_t)(row0 + r) * BB + k0 + kq * 4];
            As[(kq*4+0) * PADA + r] = a.x;
            As[(kq*4+1) * PADA + r] = a.y;
            As[(kq*4+2) * PADA + r] = a.z;
            As[(kq*4+3) * PADA + r] = a.w;
        }
        #pragma unroll
        for (int i = 0; i < 2; i++) {
            int lin = i * 512 + t;
            int kk = lin >> 5, cq = lin & 31;
            ((float4*)Bs)[kk * 32 + cq] =
                *(const float4*)&v[(size_t)(k0 + kk) * JS + col0 + cq * 4];
        }
        __syncthreads();
        #pragma unroll 8
        for (int kk = 0; kk < 32; kk++) {
            float4 a = *(const float4*)&As[kk * PADA + tr * 4];
            const ulonglong2* bpp = (const ulonglong2*)&Bs[kk * 128 + tc * 8];
            ulonglong2 b0 = bpp[0], b1 = bpp[1];
            ull a0 = pk2(a.x, a.x), a1 = pk2(a.y, a.y);
            ull a2 = pk2(a.z, a.z), a3 = pk2(a.w, a.w);
            fma2(acc[0][0], b0.x, a0); fma2(acc[0][1], b0.y, a0);
            fma2(acc[0][2], b1.x, a0); fma2(acc[0][3], b1.y, a0);
            fma2(acc[1][0], b0.x, a1); fma2(acc[1][1], b0.y, a1);
            fma2(acc[1][2], b1.x, a1); fma2(acc[1][3], b1.y, a1);
            fma2(acc[2][0], b0.x, a2); fma2(acc[2][1], b0.y, a2);
            fma2(acc[2][2], b1.x, a2); fma2(acc[2][3], b1.y, a2);
            fma2(acc[3][0], b0.x, a3); fma2(acc[3][1], b0.y, a3);
            fma2(acc[3][2], b1.x, a3); fma2(acc[3][3], b1.y, a3);
        }
        __syncthreads();
    }

    // epilogue: partial b-update. Thread cols = (one j_local, 8 s starting at s0).
    int u  = row0 >> 11;             // row0 / 2048
    int jl = tc >> 1;                // j_local within 8-j block
    int j  = (col0 >> 4) + jl;       // global j
    int s0 = (tc & 1) * 8;
    #pragma unroll
    for (int ri = 0; ri < 4; ri++) {
        int c = (row0 & 2047) + tr * 4 + ri;
        const float4* wr4 = (const float4*)&g_Wr[((c * JJ + j) * UU + u) * SS + s0];
        float4 w0 = wr4[0], w1 = wr4[1];
        float m[8];
        #pragma unroll
        for (int q = 0; q < 4; q++) upk2(m[2*q], m[2*q+1], acc[ri][q]);
        float dot = w0.x*m[0] + w0.y*m[1] + w0.z*m[2] + w0.w*m[3]
                  + w1.x*m[4] + w1.y*m[5] + w1.z*m[6] + w1.w*m[7];
        float other = __shfl_xor_sync(0xffffffffu, dot, 1);
        if ((tc & 1) == 0)
            g_bp[(u * CC + c) * JJ + j] = dot + other;
    }
}

// ---------------- b[j,c] += (1/B) sum_u g_bp[u][c][j] ---------------------------
__global__ void breduce_k() {
    int idx = blockIdx.x * 256 + threadIdx.x;   // over C*J
    int c = idx >> 5, j = idx & 31;
    float acc = 0.0f;
    #pragma unroll
    for (int u = 0; u < UU; u++)
        acc += g_bp[(u * CC + c) * JJ + j];
    g_b[j * CC + c] += acc * (1.0f / (float)BB);
}

// ---------------- launcher --------------------------------------------------------
extern "C" void kernel_launch(void* const* d_in, const int* in_sizes, int n_in,
                              void* d_out, int out_size) {
    const float* x = (const float*)d_in[0];   // [B,U,C]
    const float* W = (const float*)d_in[1];   // [1,C,J,S,U]
    float* out = (float*)d_out;               // [B,J,S,1]

    transpose_x_k<<<dim3(CC/32, BB/32, UU), dim3(32, 32)>>>(x);
    reorder_w_k<<<CC*JJ/2, 256>>>(W);
    init_k<<<(JJ*CC + 255)/256, 256>>>();

    for (int it = 0; it < NITER; it++) {
        if (it > 0) softmax_k<<<JJ, 512>>>();   // iter 0: uniform coeffs from init
        s_pass_k<<<dim3(JJ, NCHUNK), 256>>>();
        squash_k<<<BB, 512>>>(out);
        if (it < NITER - 1) {
            mgemm_k<<<dim3(JS/128, UC/128), 512>>>(out);
            breduce_k<<<CC*JJ/256, 256>>>();
        }
    }
}

// round 6
// speedup vs baseline: 1.3300x; 1.0501x over previous
#include <cuda_runtime.h>

#define BB 128
#define UU 8
#define CC 2048
#define JJ 32
#define SS 16
#define NITER 3

#define JS   (JJ*SS)     // 512
#define SU   (SS*UU)     // 128
#define JSU  (JJ*SS*UU)  // 4096
#define UC   (UU*CC)     // 16384
#define CB   (CC*BB)     // 262144
#define NCHUNK 64        // 64 chunks of 32 c

typedef unsigned long long ull;

// ---------------- packed f32x2 helpers ---------------------------------------
__device__ __forceinline__ ull pk2(float lo, float hi) {
    ull r; asm("mov.b64 %0, {%1, %2};" : "=l"(r) : "f"(lo), "f"(hi)); return r;
}
__device__ __forceinline__ void fma2(ull& d, ull a, ull b) {
    asm("fma.rn.f32x2 %0, %1, %2, %0;" : "+l"(d) : "l"(a), "l"(b));
}
__device__ __forceinline__ void add2(ull& d, ull a) {
    asm("add.rn.f32x2 %0, %0, %1;" : "+l"(d) : "l"(a));
}
__device__ __forceinline__ void upk2(float& lo, float& hi, ull v) {
    asm("mov.b64 {%0, %1}, %2;" : "=f"(lo), "=f"(hi) : "l"(v));
}

// ---------------- device scratch ----------------------------------------------
__device__ float g_xT[UU*CC*BB];       // [u][c][b]  8 MB
__device__ float g_Wr[CC*JSU];         // [c][j][u][s] 33.5 MB
__device__ float g_b[JJ*CC];           // logits [j][c]
__device__ float g_c[JJ*CC];           // coeffs [j][c]
__device__ float g_sp[NCHUNK*BB*JS];   // partial s, 16 MB
__device__ float g_bp[UU*CC*JJ];       // per-u partial b-updates, 2 MB

// ---------------- transpose x -> xT[u][c][b] -----------------------------------
__global__ void transpose_x_k(const float* __restrict__ x) {
    __shared__ float tile[32][33];
    int u  = blockIdx.z;
    int c0 = blockIdx.x * 32;
    int b0 = blockIdx.y * 32;
    int tx = threadIdx.x, ty = threadIdx.y;
    tile[ty][tx] = x[(size_t)(b0 + ty) * (UU*CC) + (size_t)u * CC + c0 + tx];
    __syncthreads();
    g_xT[(size_t)u * CB + (size_t)(c0 + ty) * BB + b0 + tx] = tile[tx][ty];
}

// ---------------- reorder W[c][j][s][u] -> Wr[c][j][u][s] -----------------------
__global__ void reorder_w_k(const float* __restrict__ Wg) {
    int row = blockIdx.x * 2 + (threadIdx.x >> 7);  // c*J + j
    int t   = threadIdx.x & 127;                    // u*16+s
    int u = t >> 4, s = t & 15;
    g_Wr[(size_t)row * SU + t] = Wg[(size_t)row * SU + s * UU + u];
}

// ---------------- init: b=0, c=1/2048 (softmax of zeros) ------------------------
__global__ void init_k() {
    int i = blockIdx.x * blockDim.x + threadIdx.x;
    if (i < JJ*CC) { g_b[i] = 0.0f; g_c[i] = 1.0f / 2048.0f; }
}

// ---------------- softmax over c for each j (coalesced) -------------------------
__global__ void softmax_k() {
    int j = blockIdx.x;       // 32
    int t = threadIdx.x;      // 512
    __shared__ float redm[16];
    __shared__ float reds[16];
    const float4* bp = (const float4*)(g_b + (size_t)j * CC);
    float4 v = bp[t];
    float mx = fmaxf(fmaxf(v.x, v.y), fmaxf(v.z, v.w));
    #pragma unroll
    for (int o = 16; o > 0; o >>= 1) mx = fmaxf(mx, __shfl_xor_sync(0xffffffffu, mx, o));
    if ((t & 31) == 0) redm[t >> 5] = mx;
    __syncthreads();
    float bmax = redm[0];
    #pragma unroll
    for (int i = 1; i < 16; i++) bmax = fmaxf(bmax, redm[i]);
    float4 e;
    e.x = __expf(v.x - bmax); e.y = __expf(v.y - bmax);
    e.z = __expf(v.z - bmax); e.w = __expf(v.w - bmax);
    float sm = e.x + e.y + e.z + e.w;
    #pragma unroll
    for (int o = 16; o > 0; o >>= 1) sm += __shfl_xor_sync(0xffffffffu, sm, o);
    if ((t & 31) == 0) reds[t >> 5] = sm;
    __syncthreads();
    float tot = 0.0f;
    #pragma unroll
    for (int i = 0; i < 16; i++) tot += reds[i];
    float inv = 1.0f / tot;
    e.x *= inv; e.y *= inv; e.z *= inv; e.w *= inv;
    ((float4*)(g_c + (size_t)j * CC))[t] = e;
}

// ---------------- fused s-pass ---------------------------------------------------
// s[b,j,s] = sum_c coef[j,c] * sum_u Wr[c,j,u,s] * xT[u,c,b]
// block = (j, chunk of 32 c), 256 threads = 8 warps.
// warp w: c-group g=w>>1 (8 c), b-half h=w&1. Lane owns adjacent b-pair
// b = h*64 + lane*2 + {0,1}  (one LDG.64 per (c,u), prefetched 1 step ahead).
__global__ void __launch_bounds__(256, 3) s_pass_k() {
    int j     = blockIdx.x;   // 32
    int chunk = blockIdx.y;   // 64
    int t     = threadIdx.x;
    int w = t >> 5, lane = t & 31;
    int g = w >> 1, h = w & 1;
    int cbase = chunk * 32;

    __shared__ __align__(16) float wsm[32 * 128];  // 16 KB (stage, then reduce)

    // stage coef-scaled W: 32 c x 32 float4 = 1024 float4, 4 per thread
    {
        const float4* Wr4 = (const float4*)g_Wr;
        float4* w4 = (float4*)wsm;
        #pragma unroll
        for (int i = 0; i < 4; i++) {
            int lin = i * 256 + t;          // 0..1023
            int cl = lin >> 5, q = lin & 31;
            float coef = __ldg(&g_c[j * CC + cbase + cl]);
            float4 wv = Wr4[(size_t)(cbase + cl) * (JSU/4) + j * 32 + q];
            wv.x *= coef; wv.y *= coef; wv.z *= coef; wv.w *= coef;
            w4[cl * 32 + q] = wv;
        }
    }
    __syncthreads();

    ull acc[2][8];
    #pragma unroll
    for (int bi = 0; bi < 2; bi++)
        #pragma unroll
        for (int sp = 0; sp < 8; sp++) acc[bi][sp] = 0ULL;

    int boff2 = h * 64 + lane * 2;
    int gbase = cbase + g * 8;

    const float* xp = g_xT + gbase * BB + boff2;   // (k=0, u=0)
    float2 xv = *(const float2*)xp;

    #pragma unroll 1
    for (int k = 0; k < 8; k++) {
        int cl = g * 8 + k;
        #pragma unroll
        for (int u = 0; u < UU; u++) {
            // prefetch next (k,u) x  (last iter reads in-bounds garbage, unused)
            const float* xnp = (u < 7) ? (xp + CB) : (xp - 7 * CB + BB);
            float2 xn = *(const float2*)xnp;

            ull xd0 = pk2(xv.x, xv.x), xd1 = pk2(xv.y, xv.y);
            const ulonglong2* w2 = (const ulonglong2*)&wsm[cl * 128 + u * 16];
            ulonglong2 wv0 = w2[0], wv1 = w2[1], wv2 = w2[2], wv3 = w2[3];
            fma2(acc[0][0], wv0.x, xd0); fma2(acc[1][0], wv0.x, xd1);
            fma2(acc[0][1], wv0.y, xd0); fma2(acc[1][1], wv0.y, xd1);
            fma2(acc[0][2], wv1.x, xd0); fma2(acc[1][2], wv1.x, xd1);
            fma2(acc[0][3], wv1.y, xd0); fma2(acc[1][3], wv1.y, xd1);
            fma2(acc[0][4], wv2.x, xd0); fma2(acc[1][4], wv2.x, xd1);
            fma2(acc[0][5], wv2.y, xd0); fma2(acc[1][5], wv2.y, xd1);
            fma2(acc[0][6], wv3.x, xd0); fma2(acc[1][6], wv3.x, xd1);
            fma2(acc[0][7], wv3.y, xd0); fma2(acc[1][7], wv3.y, xd1);

            xp = xnp; xv = xn;
        }
    }

    // reduce over 4 c-groups; layout index = bi*64 + h*32 + lane (stride-1 lanes)
    __syncthreads();
    ull* redU = (ull*)wsm;   // 2048 ULL
    int sidx = h * 32 + lane;
    if (g < 2) {
        #pragma unroll
        for (int bi = 0; bi < 2; bi++)
            #pragma unroll
            for (int sp = 0; sp < 8; sp++)
                redU[g * 1024 + sp * 128 + bi * 64 + sidx] = acc[bi][sp];
    }
    __syncthreads();
    if (g >= 2) {
        #pragma unroll
        for (int bi = 0; bi < 2; bi++)
            #pragma unroll
            for (int sp = 0; sp < 8; sp++) {
                int idx = (g - 2) * 1024 + sp * 128 + bi * 64 + sidx;
                ull s = redU[idx];
                add2(s, acc[bi][sp]);
                redU[idx] = s;
            }
    }
    __syncthreads();

    // threads 0..127: slot t holds b = ((t>>5)&1)*64 + (t&31)*2 + (t>>6)
    if (t < 128) {
        int b = ((t >> 5) & 1) * 64 + (t & 31) * 2 + (t >> 6);
        float res[16];
        #pragma unroll
        for (int sp = 0; sp < 8; sp++) {
            ull s = redU[sp * 128 + t];
            add2(s, redU[1024 + sp * 128 + t]);
            upk2(res[2*sp], res[2*sp+1], s);
        }
        float4* dst = (float4*)&g_sp[(size_t)chunk * (BB*JS) + b * JS + j * SS];
        #pragma unroll
        for (int q = 0; q < 4; q++)
            dst[q] = make_float4(res[q*4], res[q*4+1], res[q*4+2], res[q*4+3]);
    }
}

// ---------------- reduce partials + squash -> v ---------------------------------
__global__ void squash_k(float* __restrict__ out) {
    int b = blockIdx.x;      // 128
    int t = threadIdx.x;     // 512
    float sv = 0.0f;
    #pragma unroll 8
    for (int k = 0; k < NCHUNK; k++)
        sv += g_sp[(size_t)k * (BB*JS) + b * JS + t];

    __shared__ float sq[512];
    __shared__ float msqs[SS];
    sq[t] = sv * sv;
    __syncthreads();
    if (t < SS) {
        float m = 0.0f;
        #pragma unroll
        for (int jj = 0; jj < JJ; jj++) m += sq[jj * SS + t];
        msqs[t] = m;
    }
    __syncthreads();
    float msq = msqs[t & (SS - 1)];
    float scale = msq / ((1.0f + msq) * sqrtf(msq));
    out[b * JS + t] = sv * scale;
}

// ---------------- fused M-GEMM + b-update epilogue ------------------------------
// M = xT(16384x128) * v(128x512); 128x64 tile, 256 thr, 4x8 per thread,
// register double-buffered K-tiles; epilogue dots with Wr -> g_bp[u][c][j].
#define PADA 132
__global__ void __launch_bounds__(256, 3) mgemm_k(const float* __restrict__ v) {
    __shared__ __align__(16) float As[32 * PADA];  // [kk][r]
    __shared__ __align__(16) float Bs[32 * 64];    // [kk][cc]
    int col0 = blockIdx.x * 64;    // 8
    int row0 = blockIdx.y * 128;   // 128 (one u-block: 128 consecutive c)
    int t  = threadIdx.x;
    int tr = t >> 3;               // 0..31 -> rows tr*4..+4
    int tc = t & 7;                // 0..7  -> cols tc*8..+8

    ull acc[4][4];
    #pragma unroll
    for (int i = 0; i < 4; i++)
        #pragma unroll
        for (int q = 0; q < 4; q++) acc[i][q] = 0ULL;

    // prefetch K-tile 0 into regs: A 1024 float4 -> 4/thread, B 512 float4 -> 2/thread
    float4 aReg[4]; float4 bReg[2];
    #pragma unroll
    for (int i = 0; i < 4; i++) {
        int lin = i * 256 + t;
        int r = lin >> 3, kq = lin & 7;
        aReg[i] = *(const float4*)&g_xT[(size_t)(row0 + r) * BB + kq * 4];
    }
    #pragma unroll
    for (int i = 0; i < 2; i++) {
        int lin = i * 256 + t;
        int kk = lin >> 4, cq = lin & 15;
        bReg[i] = *(const float4*)&v[(size_t)kk * JS + col0 + cq * 4];
    }

    for (int k0 = 0; k0 < BB; k0 += 32) {
        // store staged regs to smem
        #pragma unroll
        for (int i = 0; i < 4; i++) {
            int lin = i * 256 + t;
            int r = lin >> 3, kq = lin & 7;
            As[(kq*4+0) * PADA + r] = aReg[i].x;
            As[(kq*4+1) * PADA + r] = aReg[i].y;
            As[(kq*4+2) * PADA + r] = aReg[i].z;
            As[(kq*4+3) * PADA + r] = aReg[i].w;
        }
        #pragma unroll
        for (int i = 0; i < 2; i++) {
            int lin = i * 256 + t;
            int kk = lin >> 4, cq = lin & 15;
            ((float4*)Bs)[kk * 16 + cq] = bReg[i];
        }
        __syncthreads();

        // prefetch next K-tile
        if (k0 + 32 < BB) {
            #pragma unroll
            for (int i = 0; i < 4; i++) {
                int lin = i * 256 + t;
                int r = lin >> 3, kq = lin & 7;
                aReg[i] = *(const float4*)&g_xT[(size_t)(row0 + r) * BB + k0 + 32 + kq * 4];
            }
            #pragma unroll
            for (int i = 0; i < 2; i++) {
                int lin = i * 256 + t;
                int kk = lin >> 4, cq = lin & 15;
                bReg[i] = *(const float4*)&v[(size_t)(k0 + 32 + kk) * JS + col0 + cq * 4];
            }
        }

        #pragma unroll 8
        for (int kk = 0; kk < 32; kk++) {
            float4 a = *(const float4*)&As[kk * PADA + tr * 4];
            const ulonglong2* bpp = (const ulonglong2*)&Bs[kk * 64 + tc * 8];
            ulonglong2 b0 = bpp[0], b1 = bpp[1];
            ull a0 = pk2(a.x, a.x), a1 = pk2(a.y, a.y);
            ull a2 = pk2(a.z, a.z), a3 = pk2(a.w, a.w);
            fma2(acc[0][0], b0.x, a0); fma2(acc[0][1], b0.y, a0);
            fma2(acc[0][2], b1.x, a0); fma2(acc[0][3], b1.y, a0);
            fma2(acc[1][0], b0.x, a1); fma2(acc[1][1], b0.y, a1);
            fma2(acc[1][2], b1.x, a1); fma2(acc[1][3], b1.y, a1);
            fma2(acc[2][0], b0.x, a2); fma2(acc[2][1], b0.y, a2);
            fma2(acc[2][2], b1.x, a2); fma2(acc[2][3], b1.y, a2);
            fma2(acc[3][0], b0.x, a3); fma2(acc[3][1], b0.y, a3);
            fma2(acc[3][2], b1.x, a3); fma2(acc[3][3], b1.y, a3);
        }
        __syncthreads();
    }

    // epilogue: partial b-update. Thread cols = (one j_local, 8 s at s0).
    int u  = row0 >> 11;
    int j  = (col0 >> 4) + (tc >> 1);
    int s0 = (tc & 1) * 8;
    #pragma unroll
    for (int ri = 0; ri < 4; ri++) {
        int c = (row0 & 2047) + tr * 4 + ri;
        const float4* wr4 = (const float4*)&g_Wr[((c * JJ + j) * UU + u) * SS + s0];
        float4 w0 = wr4[0], w1 = wr4[1];
        float m[8];
        #pragma unroll
        for (int q = 0; q < 4; q++) upk2(m[2*q], m[2*q+1], acc[ri][q]);
        float dot = w0.x*m[0] + w0.y*m[1] + w0.z*m[2] + w0.w*m[3]
                  + w1.x*m[4] + w1.y*m[5] + w1.z*m[6] + w1.w*m[7];
        float other = __shfl_xor_sync(0xffffffffu, dot, 1);
        if ((tc & 1) == 0)
            g_bp[(u * CC + c) * JJ + j] = dot + other;
    }
}

// ---------------- b[j,c] += (1/B) sum_u g_bp[u][c][j] ---------------------------
__global__ void breduce_k() {
    int idx = blockIdx.x * 256 + threadIdx.x;   // over C*J
    int c = idx >> 5, j = idx & 31;
    float acc = 0.0f;
    #pragma unroll
    for (int u = 0; u < UU; u++)
        acc += g_bp[(u * CC + c) * JJ + j];
    g_b[j * CC + c] += acc * (1.0f / (float)BB);
}

// ---------------- launcher --------------------------------------------------------
extern "C" void kernel_launch(void* const* d_in, const int* in_sizes, int n_in,
                              void* d_out, int out_size) {
    const float* x = (const float*)d_in[0];   // [B,U,C]
    const float* W = (const float*)d_in[1];   // [1,C,J,S,U]
    float* out = (float*)d_out;               // [B,J,S,1]

    transpose_x_k<<<dim3(CC/32, BB/32, UU), dim3(32, 32)>>>(x);
    reorder_w_k<<<CC*JJ/2, 256>>>(W);
    init_k<<<(JJ*CC + 255)/256, 256>>>();

    for (int it = 0; it < NITER; it++) {
        if (it > 0) softmax_k<<<JJ, 512>>>();   // iter 0: uniform coeffs from init
        s_pass_k<<<dim3(JJ, NCHUNK), 256>>>();
        squash_k<<<BB, 512>>>(out);
        if (it < NITER - 1) {
            mgemm_k<<<dim3(JS/64, UC/128), 256>>>(out);
            breduce_k<<<CC*JJ/256, 256>>>();
        }
    }
}

// round 7
// speedup vs baseline: 1.6165x; 1.2154x over previous
#include <cuda_runtime.h>

#define BB 128
#define UU 8
#define CC 2048
#define JJ 32
#define SS 16
#define NITER 3

#define JS   (JJ*SS)     // 512
#define SU   (SS*UU)     // 128
#define JSU  (JJ*SS*UU)  // 4096
#define UC   (UU*CC)     // 16384
#define CB   (CC*BB)     // 262144
#define NCHUNK 64        // 64 chunks of 32 c

typedef unsigned long long ull;

// ---------------- packed f32x2 helpers ---------------------------------------
__device__ __forceinline__ ull pk2(float lo, float hi) {
    ull r; asm("mov.b64 %0, {%1, %2};" : "=l"(r) : "f"(lo), "f"(hi)); return r;
}
__device__ __forceinline__ void fma2(ull& d, ull a, ull b) {
    asm("fma.rn.f32x2 %0, %1, %2, %0;" : "+l"(d) : "l"(a), "l"(b));
}
__device__ __forceinline__ void add2(ull& d, ull a) {
    asm("add.rn.f32x2 %0, %0, %1;" : "+l"(d) : "l"(a));
}
__device__ __forceinline__ void upk2(float& lo, float& hi, ull v) {
    asm("mov.b64 {%0, %1}, %2;" : "=f"(lo), "=f"(hi) : "l"(v));
}
__device__ __forceinline__ void cpasync16(unsigned smem, const void* g) {
    asm volatile("cp.async.cg.shared.global [%0], [%1], 16;" :: "r"(smem), "l"(g));
}
#define CP_COMMIT() asm volatile("cp.async.commit_group;" ::: "memory")
#define CP_WAIT(n)  asm volatile("cp.async.wait_group %0;" :: "n"(n) : "memory")

// ---------------- device scratch ----------------------------------------------
__device__ float g_xT[UU*CC*BB];       // [u][c][b]  8 MB
__device__ float g_Wr[CC*JSU];         // [c][j][u][s] 33.5 MB
__device__ float g_b[JJ*CC];           // logits [j][c]
__device__ float g_c[JJ*CC];           // coeffs [j][c]
__device__ float g_sp[NCHUNK*BB*JS];   // partial s, 16 MB
__device__ float g_bp[UU*JJ*CC];       // per-u partial b-updates [u][j][c], 2 MB

// ---------------- transpose x -> xT[u][c][b] -----------------------------------
__global__ void transpose_x_k(const float* __restrict__ x) {
    __shared__ float tile[32][33];
    int u  = blockIdx.z;
    int c0 = blockIdx.x * 32;
    int b0 = blockIdx.y * 32;
    int tx = threadIdx.x, ty = threadIdx.y;
    tile[ty][tx] = x[(size_t)(b0 + ty) * (UU*CC) + (size_t)u * CC + c0 + tx];
    __syncthreads();
    g_xT[(size_t)u * CB + (size_t)(c0 + ty) * BB + b0 + tx] = tile[tx][ty];
}

// ---------------- reorder W[c][j][s][u] -> Wr[c][j][u][s] -----------------------
__global__ void reorder_w_k(const float* __restrict__ Wg) {
    int row = blockIdx.x * 2 + (threadIdx.x >> 7);  // c*J + j
    int t   = threadIdx.x & 127;                    // u*16+s
    int u = t >> 4, s = t & 15;
    g_Wr[(size_t)row * SU + t] = Wg[(size_t)row * SU + s * UU + u];
}

// ---------------- init: b=0, c=1/2048 (softmax of zeros) ------------------------
__global__ void init_k() {
    int i = blockIdx.x * blockDim.x + threadIdx.x;
    if (i < JJ*CC) { g_b[i] = 0.0f; g_c[i] = 1.0f / 2048.0f; }
}

// ---------------- fused s-pass (2 j per block) -----------------------------------
// s[b,j,s] = sum_c coef[j,c] * sum_u Wr[c,j,u,s] * xT[u,c,b]
// block = (j-pair, chunk of 32 c), 256 threads = 8 warps.
// warp w: c-group g=w>>1 (8 c), b-half h=w&1. Lane owns adjacent b-pair
// b = h*64 + lane*2 + {0,1}; one LDG.64 per (c,u) feeds BOTH j's.
__global__ void __launch_bounds__(256, 2) s_pass_k() {
    int j0    = blockIdx.x * 2;   // 16 j-pairs
    int chunk = blockIdx.y;       // 64
    int t     = threadIdx.x;
    int w = t >> 5, lane = t & 31;
    int g = w >> 1, h = w & 1;
    int cbase = chunk * 32;

    __shared__ __align__(16) float wsm[2 * 32 * 128];  // 32 KB (stage, then reduce)

    // stage coef-scaled W for both j's: 2048 float4 = 8 per thread
    {
        const float4* Wr4 = (const float4*)g_Wr;
        float4* w4 = (float4*)wsm;
        #pragma unroll
        for (int i = 0; i < 8; i++) {
            int lin = i * 256 + t;          // 0..2047
            int jj = lin >> 10;
            int rem = lin & 1023;
            int cl = rem >> 5, q = rem & 31;
            float coef = __ldg(&g_c[(j0 + jj) * CC + cbase + cl]);
            float4 wv = Wr4[(size_t)(cbase + cl) * (JSU/4) + (j0 + jj) * 32 + q];
            wv.x *= coef; wv.y *= coef; wv.z *= coef; wv.w *= coef;
            w4[jj * 1024 + cl * 32 + q] = wv;
        }
    }
    __syncthreads();

    ull acc[2][2][8];   // [jj][bi][sp]
    #pragma unroll
    for (int jj = 0; jj < 2; jj++)
        #pragma unroll
        for (int bi = 0; bi < 2; bi++)
            #pragma unroll
            for (int sp = 0; sp < 8; sp++) acc[jj][bi][sp] = 0ULL;

    int boff2 = h * 64 + lane * 2;
    const float* xp = g_xT + (cbase + g * 8) * BB + boff2;   // (k=0,u=0)
    float2 xv = *(const float2*)xp;

    #pragma unroll 1
    for (int k = 0; k < 8; k++) {
        int cl = g * 8 + k;
        #pragma unroll
        for (int u = 0; u < UU; u++) {
            const float* xnp = (u < 7) ? (xp + CB) : (xp - 7 * CB + BB);
            float2 xn = *(const float2*)xnp;

            ull xd0 = pk2(xv.x, xv.x), xd1 = pk2(xv.y, xv.y);
            #pragma unroll
            for (int jj = 0; jj < 2; jj++) {
                const ulonglong2* w2 =
                    (const ulonglong2*)&wsm[jj * 4096 + cl * 128 + u * 16];
                ulonglong2 wv0 = w2[0], wv1 = w2[1], wv2 = w2[2], wv3 = w2[3];
                fma2(acc[jj][0][0], wv0.x, xd0); fma2(acc[jj][1][0], wv0.x, xd1);
                fma2(acc[jj][0][1], wv0.y, xd0); fma2(acc[jj][1][1], wv0.y, xd1);
                fma2(acc[jj][0][2], wv1.x, xd0); fma2(acc[jj][1][2], wv1.x, xd1);
                fma2(acc[jj][0][3], wv1.y, xd0); fma2(acc[jj][1][3], wv1.y, xd1);
                fma2(acc[jj][0][4], wv2.x, xd0); fma2(acc[jj][1][4], wv2.x, xd1);
                fma2(acc[jj][0][5], wv2.y, xd0); fma2(acc[jj][1][5], wv2.y, xd1);
                fma2(acc[jj][0][6], wv3.x, xd0); fma2(acc[jj][1][6], wv3.x, xd1);
                fma2(acc[jj][0][7], wv3.y, xd0); fma2(acc[jj][1][7], wv3.y, xd1);
            }
            xp = xnp; xv = xn;
        }
    }

    // reduce over 4 c-groups; slot = bi*64 + h*32 + lane (stride-1 lanes)
    __syncthreads();
    ull* redU = (ull*)wsm;   // 4096 ULL
    int sidx = h * 32 + lane;
    if (g < 2) {
        #pragma unroll
        for (int jj = 0; jj < 2; jj++)
            #pragma unroll
            for (int bi = 0; bi < 2; bi++)
                #pragma unroll
                for (int sp = 0; sp < 8; sp++)
                    redU[jj*2048 + g*1024 + sp*128 + bi*64 + sidx] = acc[jj][bi][sp];
    }
    __syncthreads();
    if (g >= 2) {
        #pragma unroll
        for (int jj = 0; jj < 2; jj++)
            #pragma unroll
            for (int bi = 0; bi < 2; bi++)
                #pragma unroll
                for (int sp = 0; sp < 8; sp++) {
                    int idx = jj*2048 + (g-2)*1024 + sp*128 + bi*64 + sidx;
                    ull s = redU[idx];
                    add2(s, acc[jj][bi][sp]);
                    redU[idx] = s;
                }
    }
    __syncthreads();

    // all 256 threads: jj = t>>7, slot tt holds b = ((tt>>5)&1)*64 + (tt&31)*2 + (tt>>6)
    {
        int jj = t >> 7, tt = t & 127;
        int b = ((tt >> 5) & 1) * 64 + (tt & 31) * 2 + (tt >> 6);
        float res[16];
        #pragma unroll
        for (int sp = 0; sp < 8; sp++) {
            ull s = redU[jj*2048 + sp*128 + tt];
            add2(s, redU[jj*2048 + 1024 + sp*128 + tt]);
            upk2(res[2*sp], res[2*sp+1], s);
        }
        float4* dst = (float4*)&g_sp[(size_t)chunk * (BB*JS) + b * JS + (j0 + jj) * SS];
        #pragma unroll
        for (int q = 0; q < 4; q++)
            dst[q] = make_float4(res[q*4], res[q*4+1], res[q*4+2], res[q*4+3]);
    }
}

// ---------------- reduce partials + squash -> v ---------------------------------
__global__ void squash_k(float* __restrict__ out) {
    int b = blockIdx.x;      // 128
    int t = threadIdx.x;     // 512
    float sv = 0.0f;
    #pragma unroll 8
    for (int k = 0; k < NCHUNK; k++)
        sv += g_sp[(size_t)k * (BB*JS) + b * JS + t];

    __shared__ float sq[512];
    __shared__ float msqs[SS];
    sq[t] = sv * sv;
    __syncthreads();
    if (t < SS) {
        float m = 0.0f;
        #pragma unroll
        for (int jj = 0; jj < JJ; jj++) m += sq[jj * SS + t];
        msqs[t] = m;
    }
    __syncthreads();
    float msq = msqs[t & (SS - 1)];
    float scale = msq / ((1.0f + msq) * sqrtf(msq));
    out[b * JS + t] = sv * scale;
}

// ---------------- fused M-GEMM + b-update epilogue ------------------------------
// M[(u,c),(j,s)] = sum_b x[b][(u,c)] * v[b][(j,s)]  — A is x itself (no transpose).
// 256x64 tile, 256 thr, thread = 8 rows (f32x2 row-pairs) x 8 cols.
// cp.async double-buffered staging. Epilogue dots with Wr -> g_bp[u][j][c].
#define MG_STAGE_F 10240   // floats per stage: As 32*256=8192 + Bs 32*64=2048
__global__ void __launch_bounds__(256, 2) mgemm_k(const float* __restrict__ x,
                                                  const float* __restrict__ v) {
    extern __shared__ __align__(16) float dsm[];
    int col0 = blockIdx.x * 64;    // 8
    int row0 = blockIdx.y * 256;   // 64  (one u: 256 | 2048)
    int t  = threadIdx.x;
    int tr = t >> 3;               // 0..31 -> rows tr*8..+8
    int tc = t & 7;                // 0..7  -> cols tc*8..+8

    unsigned smem_u32;
    { unsigned long long tmp = __cvta_generic_to_shared(dsm); smem_u32 = (unsigned)tmp; }

    ull acc[4][8];   // [row-pair][col]
    #pragma unroll
    for (int i = 0; i < 4; i++)
        #pragma unroll
        for (int q = 0; q < 8; q++) acc[i][q] = 0ULL;

    // issue stage 0
    {
        unsigned sb = smem_u32;
        #pragma unroll
        for (int i = 0; i < 8; i++) {
            int lin = i * 256 + t;            // A: 2048 float4
            int kk = lin >> 6, q = lin & 63;
            cpasync16(sb + kk * 1024 + q * 16, x + (size_t)kk * UC + row0 + q * 4);
        }
        #pragma unroll
        for (int i = 0; i < 2; i++) {
            int lin = i * 256 + t;            // B: 512 float4
            int kk = lin >> 4, q = lin & 15;
            cpasync16(sb + 32768 + kk * 256 + q * 16, v + (size_t)kk * JS + col0 + q * 4);
        }
        CP_COMMIT();
    }

    #pragma unroll 1
    for (int i = 0; i < 4; i++) {
        if (i < 3) {
            int k0n = (i + 1) * 32;
            unsigned sb = smem_u32 + ((i + 1) & 1) * (MG_STAGE_F * 4);
            #pragma unroll
            for (int q8 = 0; q8 < 8; q8++) {
                int lin = q8 * 256 + t;
                int kk = lin >> 6, q = lin & 63;
                cpasync16(sb + kk * 1024 + q * 16,
                          x + (size_t)(k0n + kk) * UC + row0 + q * 4);
            }
            #pragma unroll
            for (int q2 = 0; q2 < 2; q2++) {
                int lin = q2 * 256 + t;
                int kk = lin >> 4, q = lin & 15;
                cpasync16(sb + 32768 + kk * 256 + q * 16,
                          v + (size_t)(k0n + kk) * JS + col0 + q * 4);
            }
            CP_COMMIT();
            CP_WAIT(1);
        } else {
            CP_WAIT(0);
        }
        __syncthreads();

        const float* As = dsm + (i & 1) * MG_STAGE_F;
        const float* Bs = As + 32 * 256;
        #pragma unroll 8
        for (int kk = 0; kk < 32; kk++) {
            ulonglong2 ap0 = *(const ulonglong2*)&As[kk * 256 + tr * 8];
            ulonglong2 ap1 = *(const ulonglong2*)&As[kk * 256 + tr * 8 + 4];
            float4 b0 = *(const float4*)&Bs[kk * 64 + tc * 8];
            float4 b1 = *(const float4*)&Bs[kk * 64 + tc * 8 + 4];
            ull bd[8];
            bd[0] = pk2(b0.x, b0.x); bd[1] = pk2(b0.y, b0.y);
            bd[2] = pk2(b0.z, b0.z); bd[3] = pk2(b0.w, b0.w);
            bd[4] = pk2(b1.x, b1.x); bd[5] = pk2(b1.y, b1.y);
            bd[6] = pk2(b1.z, b1.z); bd[7] = pk2(b1.w, b1.w);
            ull ap[4] = {ap0.x, ap0.y, ap1.x, ap1.y};
            #pragma unroll
            for (int rp = 0; rp < 4; rp++)
                #pragma unroll
                for (int q = 0; q < 8; q++)
                    fma2(acc[rp][q], ap[rp], bd[q]);
        }
        __syncthreads();
    }

    // epilogue: thread cols = (one j, 8 s at s0); rows tr*8..+8 (pairs).
    int u  = row0 >> 11;
    int j  = (col0 >> 4) + (tc >> 1);
    int s0 = (tc & 1) * 8;
    #pragma unroll
    for (int rp = 0; rp < 4; rp++) {
        int clo = (row0 & 2047) + tr * 8 + rp * 2;
        float mlo[8], mhi[8];
        #pragma unroll
        for (int q = 0; q < 8; q++) upk2(mlo[q], mhi[q], acc[rp][q]);
        const float4* wlo = (const float4*)&g_Wr[(((size_t)clo * JJ + j) * UU + u) * SS + s0];
        const float4* whi = (const float4*)&g_Wr[(((size_t)(clo+1) * JJ + j) * UU + u) * SS + s0];
        float4 wl0 = wlo[0], wl1 = wlo[1];
        float4 wh0 = whi[0], wh1 = whi[1];
        float dlo = wl0.x*mlo[0] + wl0.y*mlo[1] + wl0.z*mlo[2] + wl0.w*mlo[3]
                  + wl1.x*mlo[4] + wl1.y*mlo[5] + wl1.z*mlo[6] + wl1.w*mlo[7];
        float dhi = wh0.x*mhi[0] + wh0.y*mhi[1] + wh0.z*mhi[2] + wh0.w*mhi[3]
                  + wh1.x*mhi[4] + wh1.y*mhi[5] + wh1.z*mhi[6] + wh1.w*mhi[7];
        float olo = __shfl_xor_sync(0xffffffffu, dlo, 1);
        float ohi = __shfl_xor_sync(0xffffffffu, dhi, 1);
        if ((tc & 1) == 0) {
            g_bp[((size_t)u * JJ + j) * CC + clo]     = dlo + olo;
            g_bp[((size_t)u * JJ + j) * CC + clo + 1] = dhi + ohi;
        }
    }
}

// ---------------- fused b-update reduce + softmax -------------------------------
__global__ void bsoftmax_k() {
    int j = blockIdx.x;       // 32
    int t = threadIdx.x;      // 512
    __shared__ float redm[16];
    __shared__ float reds[16];
    float4 bv = ((const float4*)(g_b + (size_t)j * CC))[t];
    float4 su = make_float4(0.f, 0.f, 0.f, 0.f);
    #pragma unroll
    for (int u = 0; u < UU; u++) {
        float4 p = ((const float4*)(g_bp + ((size_t)u * JJ + j) * CC))[t];
        su.x += p.x; su.y += p.y; su.z += p.z; su.w += p.w;
    }
    const float inv_b = 1.0f / (float)BB;
    bv.x += su.x * inv_b; bv.y += su.y * inv_b;
    bv.z += su.z * inv_b; bv.w += su.w * inv_b;
    ((float4*)(g_b + (size_t)j * CC))[t] = bv;

    float mx = fmaxf(fmaxf(bv.x, bv.y), fmaxf(bv.z, bv.w));
    #pragma unroll
    for (int o = 16; o > 0; o >>= 1) mx = fmaxf(mx, __shfl_xor_sync(0xffffffffu, mx, o));
    if ((t & 31) == 0) redm[t >> 5] = mx;
    __syncthreads();
    float bmax = redm[0];
    #pragma unroll
    for (int i = 1; i < 16; i++) bmax = fmaxf(bmax, redm[i]);
    float4 e;
    e.x = __expf(bv.x - bmax); e.y = __expf(bv.y - bmax);
    e.z = __expf(bv.z - bmax); e.w = __expf(bv.w - bmax);
    float sm = e.x + e.y + e.z + e.w;
    #pragma unroll
    for (int o = 16; o > 0; o >>= 1) sm += __shfl_xor_sync(0xffffffffu, sm, o);
    if ((t & 31) == 0) reds[t >> 5] = sm;
    __syncthreads();
    float tot = 0.0f;
    #pragma unroll
    for (int i = 0; i < 16; i++) tot += reds[i];
    float inv = 1.0f / tot;
    e.x *= inv; e.y *= inv; e.z *= inv; e.w *= inv;
    ((float4*)(g_c + (size_t)j * CC))[t] = e;
}

// ---------------- launcher --------------------------------------------------------
extern "C" void kernel_launch(void* const* d_in, const int* in_sizes, int n_in,
                              void* d_out, int out_size) {
    const float* x = (const float*)d_in[0];   // [B,U,C]
    const float* W = (const float*)d_in[1];   // [1,C,J,S,U]
    float* out = (float*)d_out;               // [B,J,S,1]

    cudaFuncSetAttribute(mgemm_k, cudaFuncAttributeMaxDynamicSharedMemorySize,
                         2 * MG_STAGE_F * 4);

    transpose_x_k<<<dim3(CC/32, BB/32, UU), dim3(32, 32)>>>(x);
    reorder_w_k<<<CC*JJ/2, 256>>>(W);
    init_k<<<(JJ*CC + 255)/256, 256>>>();

    for (int it = 0; it < NITER; it++) {
        s_pass_k<<<dim3(JJ/2, NCHUNK), 256>>>();
        squash_k<<<BB, 512>>>(out);
        if (it < NITER - 1) {
            mgemm_k<<<dim3(JS/64, UC/256), 256, 2 * MG_STAGE_F * 4>>>(x, out);
            bsoftmax_k<<<JJ, 512>>>();
        }
    }
}

// round 8
// speedup vs baseline: 1.6485x; 1.0198x over previous
#include <cuda_runtime.h>

#define BB 128
#define UU 8
#define CC 2048
#define JJ 32
#define SS 16
#define NITER 3

#define JS   (JJ*SS)     // 512
#define SU   (SS*UU)     // 128
#define JSU  (JJ*SS*UU)  // 4096
#define UC   (UU*CC)     // 16384
#define CB   (CC*BB)     // 262144
#define NCHUNK 64        // 64 chunks of 32 c

typedef unsigned long long ull;

// ---------------- packed f32x2 helpers ---------------------------------------
__device__ __forceinline__ ull pk2(float lo, float hi) {
    ull r; asm("mov.b64 %0, {%1, %2};" : "=l"(r) : "f"(lo), "f"(hi)); return r;
}
__device__ __forceinline__ void fma2(ull& d, ull a, ull b) {
    asm("fma.rn.f32x2 %0, %1, %2, %0;" : "+l"(d) : "l"(a), "l"(b));
}
__device__ __forceinline__ void add2(ull& d, ull a) {
    asm("add.rn.f32x2 %0, %0, %1;" : "+l"(d) : "l"(a));
}
__device__ __forceinline__ void upk2(float& lo, float& hi, ull v) {
    asm("mov.b64 {%0, %1}, %2;" : "=f"(lo), "=f"(hi) : "l"(v));
}
__device__ __forceinline__ void cpasync16(unsigned smem, const void* g) {
    asm volatile("cp.async.cg.shared.global [%0], [%1], 16;" :: "r"(smem), "l"(g));
}
#define CP_COMMIT() asm volatile("cp.async.commit_group;" ::: "memory")
#define CP_WAIT(n)  asm volatile("cp.async.wait_group %0;" :: "n"(n) : "memory")

// ---------------- device scratch ----------------------------------------------
__device__ float g_xT[UU*CC*BB];       // [u][c][b]  8 MB
__device__ float g_Wr[CC*JSU];         // [c][j][u][s] 33.5 MB
__device__ float g_b[JJ*CC];           // logits [j][c]
__device__ float g_c[JJ*CC];           // coeffs [j][c]
__device__ float g_sp[NCHUNK*BB*JS];   // partial s, 16 MB
__device__ float g_bp[UU*JJ*CC];       // per-u partial b-updates [u][j][c], 2 MB

// ---------------- transpose x -> xT[u][c][b] -----------------------------------
__global__ void transpose_x_k(const float* __restrict__ x) {
    __shared__ float tile[32][33];
    int u  = blockIdx.z;
    int c0 = blockIdx.x * 32;
    int b0 = blockIdx.y * 32;
    int tx = threadIdx.x, ty = threadIdx.y;
    tile[ty][tx] = x[(size_t)(b0 + ty) * (UU*CC) + (size_t)u * CC + c0 + tx];
    __syncthreads();
    g_xT[(size_t)u * CB + (size_t)(c0 + ty) * BB + b0 + tx] = tile[tx][ty];
}

// ---------------- reorder W[c][j][s][u] -> Wr[c][j][u][s] -----------------------
__global__ void reorder_w_k(const float* __restrict__ Wg) {
    int row = blockIdx.x * 2 + (threadIdx.x >> 7);  // c*J + j
    int t   = threadIdx.x & 127;                    // u*16+s
    int u = t >> 4, s = t & 15;
    g_Wr[(size_t)row * SU + t] = Wg[(size_t)row * SU + s * UU + u];
}

// ---------------- init: b=0, c=1/2048 (softmax of zeros) ------------------------
__global__ void init_k() {
    int i = blockIdx.x * blockDim.x + threadIdx.x;
    if (i < JJ*CC) { g_b[i] = 0.0f; g_c[i] = 1.0f / 2048.0f; }
}

// ---------------- fused s-pass (warp-split over j, b-half, c-half) ---------------
// s[b,j,s] = sum_c coef[j,c] * sum_u Wr[c,j,u,s] * xT[u,c,b]
// block = (j-pair, chunk of 32 c), 256 threads = 8 warps.
// warp w: g = w>>2 (c-half, 16 c), h = (w>>1)&1 (b-half), jj = w&1 (j).
// Lane owns adjacent b-pair b = h*64 + lane*2 + {0,1}; acc = 2b x 16s = 16 ULL.
__global__ void __launch_bounds__(256, 3) s_pass_k() {
    int j0    = blockIdx.x * 2;   // 16 j-pairs
    int chunk = blockIdx.y;       // 64
    int t     = threadIdx.x;
    int w = t >> 5, lane = t & 31;
    int g = w >> 2, h = (w >> 1) & 1, jj = w & 1;
    int cbase = chunk * 32;

    __shared__ __align__(16) float wsm[2 * 32 * 128];  // 32 KB (stage, then reduce)

    // stage coef-scaled W for both j's: 2048 float4 = 8 per thread
    {
        const float4* Wr4 = (const float4*)g_Wr;
        float4* w4 = (float4*)wsm;
        #pragma unroll
        for (int i = 0; i < 8; i++) {
            int lin = i * 256 + t;          // 0..2047
            int sj = lin >> 10;
            int rem = lin & 1023;
            int cl = rem >> 5, q = rem & 31;
            float coef = __ldg(&g_c[(j0 + sj) * CC + cbase + cl]);
            float4 wv = Wr4[(size_t)(cbase + cl) * (JSU/4) + (j0 + sj) * 32 + q];
            wv.x *= coef; wv.y *= coef; wv.z *= coef; wv.w *= coef;
            w4[sj * 1024 + cl * 32 + q] = wv;
        }
    }
    __syncthreads();

    ull acc[2][8];   // [bi][sp]
    #pragma unroll
    for (int bi = 0; bi < 2; bi++)
        #pragma unroll
        for (int sp = 0; sp < 8; sp++) acc[bi][sp] = 0ULL;

    int boff2 = h * 64 + lane * 2;
    const float* xp = g_xT + (cbase + g * 16) * BB + boff2;   // (k=0,u=0)
    float2 xv = *(const float2*)xp;
    const float* wbase = &wsm[jj * 4096 + g * 16 * 128];

    #pragma unroll 1
    for (int k = 0; k < 16; k++) {
        #pragma unroll
        for (int u = 0; u < UU; u++) {
            const float* xnp = (u < 7) ? (xp + CB) : (xp - 7 * CB + BB);
            float2 xn = *(const float2*)xnp;

            ull xd0 = pk2(xv.x, xv.x), xd1 = pk2(xv.y, xv.y);
            const ulonglong2* w2 = (const ulonglong2*)(wbase + k * 128 + u * 16);
            ulonglong2 wv0 = w2[0], wv1 = w2[1], wv2 = w2[2], wv3 = w2[3];
            fma2(acc[0][0], wv0.x, xd0); fma2(acc[1][0], wv0.x, xd1);
            fma2(acc[0][1], wv0.y, xd0); fma2(acc[1][1], wv0.y, xd1);
            fma2(acc[0][2], wv1.x, xd0); fma2(acc[1][2], wv1.x, xd1);
            fma2(acc[0][3], wv1.y, xd0); fma2(acc[1][3], wv1.y, xd1);
            fma2(acc[0][4], wv2.x, xd0); fma2(acc[1][4], wv2.x, xd1);
            fma2(acc[0][5], wv2.y, xd0); fma2(acc[1][5], wv2.y, xd1);
            fma2(acc[0][6], wv3.x, xd0); fma2(acc[1][6], wv3.x, xd1);
            fma2(acc[0][7], wv3.y, xd0); fma2(acc[1][7], wv3.y, xd1);

            xp = xnp; xv = xn;
        }
    }

    // reduce over 2 c-halves: g=0 stores, g=1 adds + writes out directly
    __syncthreads();
    ull* redU = (ull*)wsm;   // 2048 ULL = 16 KB
    int sidx = h * 32 + lane;
    if (g == 0) {
        #pragma unroll
        for (int bi = 0; bi < 2; bi++)
            #pragma unroll
            for (int sp = 0; sp < 8; sp++)
                redU[jj * 1024 + sp * 128 + bi * 64 + sidx] = acc[bi][sp];
    }
    __syncthreads();
    if (g == 1) {
        #pragma unroll
        for (int bi = 0; bi < 2; bi++) {
            float rb[16];
            #pragma unroll
            for (int sp = 0; sp < 8; sp++) {
                ull s = redU[jj * 1024 + sp * 128 + bi * 64 + sidx];
                add2(s, acc[bi][sp]);
                upk2(rb[2*sp], rb[2*sp+1], s);
            }
            int b = boff2 + bi;
            float4* dst = (float4*)&g_sp[(size_t)chunk * (BB*JS) + b * JS + (j0 + jj) * SS];
            #pragma unroll
            for (int q = 0; q < 4; q++)
                dst[q] = make_float4(rb[q*4], rb[q*4+1], rb[q*4+2], rb[q*4+3]);
        }
    }
}

// ---------------- reduce partials + squash -> v ---------------------------------
__global__ void squash_k(float* __restrict__ out) {
    int b = blockIdx.x;      // 128
    int t = threadIdx.x;     // 512
    float sv = 0.0f;
    #pragma unroll 8
    for (int k = 0; k < NCHUNK; k++)
        sv += g_sp[(size_t)k * (BB*JS) + b * JS + t];

    __shared__ float sq[512];
    __shared__ float msqs[SS];
    sq[t] = sv * sv;
    __syncthreads();
    if (t < SS) {
        float m = 0.0f;
        #pragma unroll
        for (int jj = 0; jj < JJ; jj++) m += sq[jj * SS + t];
        msqs[t] = m;
    }
    __syncthreads();
    float msq = msqs[t & (SS - 1)];
    float scale = msq / ((1.0f + msq) * sqrtf(msq));
    out[b * JS + t] = sv * scale;
}

// ---------------- fused M-GEMM + b-update epilogue ------------------------------
// M[(u,c),(j,s)] = sum_b x[b][(u,c)] * v[b][(j,s)]  — A is x itself (no transpose).
// 256x64 tile, 256 thr, thread = 8 rows (f32x2 row-pairs) x 8 cols.
// cp.async double-buffered staging. Epilogue dots with Wr -> g_bp[u][j][c].
#define MG_STAGE_F 10240   // floats per stage: As 32*256=8192 + Bs 32*64=2048
__global__ void __launch_bounds__(256, 2) mgemm_k(const float* __restrict__ x,
                                                  const float* __restrict__ v) {
    extern __shared__ __align__(16) float dsm[];
    int col0 = blockIdx.x * 64;    // 8
    int row0 = blockIdx.y * 256;   // 64  (one u: 256 | 2048)
    int t  = threadIdx.x;
    int tr = t >> 3;               // 0..31 -> rows tr*8..+8
    int tc = t & 7;                // 0..7  -> cols tc*8..+8

    unsigned smem_u32;
    { unsigned long long tmp = __cvta_generic_to_shared(dsm); smem_u32 = (unsigned)tmp; }

    ull acc[4][8];   // [row-pair][col]
    #pragma unroll
    for (int i = 0; i < 4; i++)
        #pragma unroll
        for (int q = 0; q < 8; q++) acc[i][q] = 0ULL;

    // issue stage 0
    {
        unsigned sb = smem_u32;
        #pragma unroll
        for (int i = 0; i < 8; i++) {
            int lin = i * 256 + t;            // A: 2048 float4
            int kk = lin >> 6, q = lin & 63;
            cpasync16(sb + kk * 1024 + q * 16, x + (size_t)kk * UC + row0 + q * 4);
        }
        #pragma unroll
        for (int i = 0; i < 2; i++) {
            int lin = i * 256 + t;            // B: 512 float4
            int kk = lin >> 4, q = lin & 15;
            cpasync16(sb + 32768 + kk * 256 + q * 16, v + (size_t)kk * JS + col0 + q * 4);
        }
        CP_COMMIT();
    }

    #pragma unroll 1
    for (int i = 0; i < 4; i++) {
        if (i < 3) {
            int k0n = (i + 1) * 32;
            unsigned sb = smem_u32 + ((i + 1) & 1) * (MG_STAGE_F * 4);
            #pragma unroll
            for (int q8 = 0; q8 < 8; q8++) {
                int lin = q8 * 256 + t;
                int kk = lin >> 6, q = lin & 63;
                cpasync16(sb + kk * 1024 + q * 16,
                          x + (size_t)(k0n + kk) * UC + row0 + q * 4);
            }
            #pragma unroll
            for (int q2 = 0; q2 < 2; q2++) {
                int lin = q2 * 256 + t;
                int kk = lin >> 4, q = lin & 15;
                cpasync16(sb + 32768 + kk * 256 + q * 16,
                          v + (size_t)(k0n + kk) * JS + col0 + q * 4);
            }
            CP_COMMIT();
            CP_WAIT(1);
        } else {
            CP_WAIT(0);
        }
        __syncthreads();

        const float* As = dsm + (i & 1) * MG_STAGE_F;
        const float* Bs = As + 32 * 256;
        #pragma unroll 8
        for (int kk = 0; kk < 32; kk++) {
            ulonglong2 ap0 = *(const ulonglong2*)&As[kk * 256 + tr * 8];
            ulonglong2 ap1 = *(const ulonglong2*)&As[kk * 256 + tr * 8 + 4];
            float4 b0 = *(const float4*)&Bs[kk * 64 + tc * 8];
            float4 b1 = *(const float4*)&Bs[kk * 64 + tc * 8 + 4];
            ull bd[8];
            bd[0] = pk2(b0.x, b0.x); bd[1] = pk2(b0.y, b0.y);
            bd[2] = pk2(b0.z, b0.z); bd[3] = pk2(b0.w, b0.w);
            bd[4] = pk2(b1.x, b1.x); bd[5] = pk2(b1.y, b1.y);
            bd[6] = pk2(b1.z, b1.z); bd[7] = pk2(b1.w, b1.w);
            ull ap[4] = {ap0.x, ap0.y, ap1.x, ap1.y};
            #pragma unroll
            for (int rp = 0; rp < 4; rp++)
                #pragma unroll
                for (int q = 0; q < 8; q++)
                    fma2(acc[rp][q], ap[rp], bd[q]);
        }
        __syncthreads();
    }

    // epilogue: thread cols = (one j, 8 s at s0); rows tr*8..+8 (pairs).
    int u  = row0 >> 11;
    int j  = (col0 >> 4) + (tc >> 1);
    int s0 = (tc & 1) * 8;
    #pragma unroll
    for (int rp = 0; rp < 4; rp++) {
        int clo = (row0 & 2047) + tr * 8 + rp * 2;
        float mlo[8], mhi[8];
        #pragma unroll
        for (int q = 0; q < 8; q++) upk2(mlo[q], mhi[q], acc[rp][q]);
        const float4* wlo = (const float4*)&g_Wr[(((size_t)clo * JJ + j) * UU + u) * SS + s0];
        const float4* whi = (const float4*)&g_Wr[(((size_t)(clo+1) * JJ + j) * UU + u) * SS + s0];
        float4 wl0 = wlo[0], wl1 = wlo[1];
        float4 wh0 = whi[0], wh1 = whi[1];
        float dlo = wl0.x*mlo[0] + wl0.y*mlo[1] + wl0.z*mlo[2] + wl0.w*mlo[3]
                  + wl1.x*mlo[4] + wl1.y*mlo[5] + wl1.z*mlo[6] + wl1.w*mlo[7];
        float dhi = wh0.x*mhi[0] + wh0.y*mhi[1] + wh0.z*mhi[2] + wh0.w*mhi[3]
                  + wh1.x*mhi[4] + wh1.y*mhi[5] + wh1.z*mhi[6] + wh1.w*mhi[7];
        float olo = __shfl_xor_sync(0xffffffffu, dlo, 1);
        float ohi = __shfl_xor_sync(0xffffffffu, dhi, 1);
        if ((tc & 1) == 0) {
            g_bp[((size_t)u * JJ + j) * CC + clo]     = dlo + olo;
            g_bp[((size_t)u * JJ + j) * CC + clo + 1] = dhi + ohi;
        }
    }
}

// ---------------- fused b-update reduce + softmax -------------------------------
__global__ void bsoftmax_k() {
    int j = blockIdx.x;       // 32
    int t = threadIdx.x;      // 512
    __shared__ float redm[16];
    __shared__ float reds[16];
    float4 bv = ((const float4*)(g_b + (size_t)j * CC))[t];
    float4 su = make_float4(0.f, 0.f, 0.f, 0.f);
    #pragma unroll
    for (int u = 0; u < UU; u++) {
        float4 p = ((const float4*)(g_bp + ((size_t)u * JJ + j) * CC))[t];
        su.x += p.x; su.y += p.y; su.z += p.z; su.w += p.w;
    }
    const float inv_b = 1.0f / (float)BB;
    bv.x += su.x * inv_b; bv.y += su.y * inv_b;
    bv.z += su.z * inv_b; bv.w += su.w * inv_b;
    ((float4*)(g_b + (size_t)j * CC))[t] = bv;

    float mx = fmaxf(fmaxf(bv.x, bv.y), fmaxf(bv.z, bv.w));
    #pragma unroll
    for (int o = 16; o > 0; o >>= 1) mx = fmaxf(mx, __shfl_xor_sync(0xffffffffu, mx, o));
    if ((t & 31) == 0) redm[t >> 5] = mx;
    __syncthreads();
    float bmax = redm[0];
    #pragma unroll
    for (int i = 1; i < 16; i++) bmax = fmaxf(bmax, redm[i]);
    float4 e;
    e.x = __expf(bv.x - bmax); e.y = __expf(bv.y - bmax);
    e.z = __expf(bv.z - bmax); e.w = __expf(bv.w - bmax);
    float sm = e.x + e.y + e.z + e.w;
    #pragma unroll
    for (int o = 16; o > 0; o >>= 1) sm += __shfl_xor_sync(0xffffffffu, sm, o);
    if ((t & 31) == 0) reds[t >> 5] = sm;
    __syncthreads();
    float tot = 0.0f;
    #pragma unroll
    for (int i = 0; i < 16; i++) tot += reds[i];
    float inv = 1.0f / tot;
    e.x *= inv; e.y *= inv; e.z *= inv; e.w *= inv;
    ((float4*)(g_c + (size_t)j * CC))[t] = e;
}

// ---------------- launcher --------------------------------------------------------
extern "C" void kernel_launch(void* const* d_in, const int* in_sizes, int n_in,
                              void* d_out, int out_size) {
    const float* x = (const float*)d_in[0];   // [B,U,C]
    const float* W = (const float*)d_in[1];   // [1,C,J,S,U]
    float* out = (float*)d_out;               // [B,J,S,1]

    cudaFuncSetAttribute(mgemm_k, cudaFuncAttributeMaxDynamicSharedMemorySize,
                         2 * MG_STAGE_F * 4);

    transpose_x_k<<<dim3(CC/32, BB/32, UU), dim3(32, 32)>>>(x);
    reorder_w_k<<<CC*JJ/2, 256>>>(W);
    init_k<<<(JJ*CC + 255)/256, 256>>>();

    for (int it = 0; it < NITER; it++) {
        s_pass_k<<<dim3(JJ/2, NCHUNK), 256>>>();
        squash_k<<<BB, 512>>>(out);
        if (it < NITER - 1) {
            mgemm_k<<<dim3(JS/64, UC/256), 256, 2 * MG_STAGE_F * 4>>>(x, out);
            bsoftmax_k<<<JJ, 512>>>();
        }
    }
}

// round 9
// speedup vs baseline: 1.7190x; 1.0428x over previous
#include <cuda_runtime.h>

#define BB 128
#define UU 8
#define CC 2048
#define JJ 32
#define SS 16
#define NITER 3

#define JS   (JJ*SS)     // 512
#define SU   (SS*UU)     // 128
#define JSU  (JJ*SS*UU)  // 4096
#define UC   (UU*CC)     // 16384
#define CB   (CC*BB)     // 262144
#define NCHUNK 64        // 64 chunks of 32 c

typedef unsigned long long ull;

// ---------------- packed f32x2 helpers ---------------------------------------
__device__ __forceinline__ ull pk2(float lo, float hi) {
    ull r; asm("mov.b64 %0, {%1, %2};" : "=l"(r) : "f"(lo), "f"(hi)); return r;
}
__device__ __forceinline__ void fma2(ull& d, ull a, ull b) {
    asm("fma.rn.f32x2 %0, %1, %2, %0;" : "+l"(d) : "l"(a), "l"(b));
}
__device__ __forceinline__ void add2(ull& d, ull a) {
    asm("add.rn.f32x2 %0, %0, %1;" : "+l"(d) : "l"(a));
}
__device__ __forceinline__ void upk2(float& lo, float& hi, ull v) {
    asm("mov.b64 {%0, %1}, %2;" : "=f"(lo), "=f"(hi) : "l"(v));
}
__device__ __forceinline__ void cpasync16(unsigned smem, const void* g) {
    asm volatile("cp.async.cg.shared.global [%0], [%1], 16;" :: "r"(smem), "l"(g));
}
#define CP_COMMIT() asm volatile("cp.async.commit_group;" ::: "memory")
#define CP_WAIT(n)  asm volatile("cp.async.wait_group %0;" :: "n"(n) : "memory")

// ---------------- device scratch ----------------------------------------------
__device__ float g_xT[UU*CC*BB + 128];   // [u][c][b]  8 MB (+pad for prefetch)
__device__ float g_Wr[CC*JSU];           // [c][j][u][s] 33.5 MB
__device__ float g_b[JJ*CC];             // logits [j][c]
__device__ float g_c[JJ*CC];             // coeffs [j][c]
__device__ float g_sp[NCHUNK*BB*JS];     // partial s, 16 MB
__device__ float g_bp[UU*JJ*CC];         // per-u partial b-updates [u][j][c], 2 MB

// ---------------- transpose x -> xT[u][c][b] -----------------------------------
__global__ void transpose_x_k(const float* __restrict__ x) {
    __shared__ float tile[32][33];
    int u  = blockIdx.z;
    int c0 = blockIdx.x * 32;
    int b0 = blockIdx.y * 32;
    int tx = threadIdx.x, ty = threadIdx.y;
    tile[ty][tx] = x[(size_t)(b0 + ty) * (UU*CC) + (size_t)u * CC + c0 + tx];
    __syncthreads();
    g_xT[(size_t)u * CB + (size_t)(c0 + ty) * BB + b0 + tx] = tile[tx][ty];
}

// ---------------- reorder W[c][j][s][u] -> Wr[c][j][u][s] -----------------------
__global__ void reorder_w_k(const float* __restrict__ Wg) {
    int row = blockIdx.x * 2 + (threadIdx.x >> 7);  // c*J + j
    int t   = threadIdx.x & 127;                    // u*16+s
    int u = t >> 4, s = t & 15;
    g_Wr[(size_t)row * SU + t] = Wg[(size_t)row * SU + s * UU + u];
}

// ---------------- init: b=0, c=1/2048 (softmax of zeros) ------------------------
__global__ void init_k() {
    int i = blockIdx.x * blockDim.x + threadIdx.x;
    if (i < JJ*CC) { g_b[i] = 0.0f; g_c[i] = 1.0f / 2048.0f; }
}

// ---------------- fused s-pass (warp = 1 j, 8 c, all 128 b, 16 s) ----------------
// s[b,j,s] = sum_c coef[j,c] * sum_u Wr[c,j,u,s] * xT[u,c,b]
// block = (j-pair, chunk of 32 c), 256 threads = 8 warps.
// warp w: jj = w&1 (j), cq = w>>1 (c-quarter, 8 c). Lane owns b = lane*4..+3
// (LDG.128, depth-2 prefetch). acc = 4b x 8sp = 32 ULL. 32 fma2 per (c,u)
// against 4 broadcast LDS.128 -> crossbar-balanced.
__global__ void __launch_bounds__(256, 2) s_pass_k() {
    int j0    = blockIdx.x * 2;   // 16 j-pairs
    int chunk = blockIdx.y;       // 64
    int t     = threadIdx.x;
    int w = t >> 5, lane = t & 31;
    int jj = w & 1, cq = w >> 1;  // cq 0..3
    int cbase = chunk * 32;

    __shared__ __align__(16) float wsm[2 * 32 * 128];  // 32 KB (stage, then reduce)

    // stage coef-scaled W for both j's: 2048 float4 = 8 per thread
    {
        const float4* Wr4 = (const float4*)g_Wr;
        float4* w4 = (float4*)wsm;
        #pragma unroll
        for (int i = 0; i < 8; i++) {
            int lin = i * 256 + t;          // 0..2047
            int sj = lin >> 10;
            int rem = lin & 1023;
            int cl = rem >> 5, q = rem & 31;
            float coef = __ldg(&g_c[(j0 + sj) * CC + cbase + cl]);
            float4 wv = Wr4[(size_t)(cbase + cl) * (JSU/4) + (j0 + sj) * 32 + q];
            wv.x *= coef; wv.y *= coef; wv.z *= coef; wv.w *= coef;
            w4[sj * 1024 + cl * 32 + q] = wv;
        }
    }
    __syncthreads();

    ull acc[4][8];   // [bi][sp]
    #pragma unroll
    for (int bi = 0; bi < 4; bi++)
        #pragma unroll
        for (int sp = 0; sp < 8; sp++) acc[bi][sp] = 0ULL;

    const float* xrow0 = g_xT + (size_t)(cbase + cq * 8) * BB + lane * 4;  // (k,u)=(0,0)
    const float* wwarp = &wsm[jj * 4096 + cq * 8 * 128];

    // depth-2 prefetch pipeline over flattened (k,u)
    float4 x0 = *(const float4*)(xrow0);            // (0,0)
    float4 x1 = *(const float4*)(xrow0 + CB);       // (0,1)

    #pragma unroll 1
    for (int k = 0; k < 8; k++) {
        const float* xrow = xrow0 + k * BB;
        #pragma unroll
        for (int u = 0; u < UU; u++) {
            // prefetch (k,u)+2 : offset ((u+2)&7)*CB + ((u+2)>>3)*BB  (compile-time)
            float4 x2 = *(const float4*)(xrow + ((u + 2) & 7) * CB + ((u + 2) >> 3) * BB);

            ull xd0 = pk2(x0.x, x0.x), xd1 = pk2(x0.y, x0.y);
            ull xd2 = pk2(x0.z, x0.z), xd3 = pk2(x0.w, x0.w);
            const ulonglong2* w2 = (const ulonglong2*)(wwarp + k * 128 + u * 16);
            ulonglong2 wv0 = w2[0], wv1 = w2[1], wv2 = w2[2], wv3 = w2[3];
            ull wp[8] = {wv0.x, wv0.y, wv1.x, wv1.y, wv2.x, wv2.y, wv3.x, wv3.y};
            #pragma unroll
            for (int sp = 0; sp < 8; sp++) {
                fma2(acc[0][sp], wp[sp], xd0);
                fma2(acc[1][sp], wp[sp], xd1);
                fma2(acc[2][sp], wp[sp], xd2);
                fma2(acc[3][sp], wp[sp], xd3);
            }
            x0 = x1; x1 = x2;
        }
    }

    // reduce over 4 c-quarters: cq{2,3} store regions {0,1}; cq{0,1} add into them;
    // then all threads sum region0+region1. slot = bi*32 + lane (conflict-free).
    __syncthreads();
    ull* redU = (ull*)wsm;   // 4096 ULL = 32 KB
    if (cq >= 2) {
        #pragma unroll
        for (int bi = 0; bi < 4; bi++)
            #pragma unroll
            for (int sp = 0; sp < 8; sp++)
                redU[jj*2048 + (cq-2)*1024 + sp*128 + bi*32 + lane] = acc[bi][sp];
    }
    __syncthreads();
    if (cq < 2) {
        #pragma unroll
        for (int bi = 0; bi < 4; bi++)
            #pragma unroll
            for (int sp = 0; sp < 8; sp++) {
                int idx = jj*2048 + cq*1024 + sp*128 + bi*32 + lane;
                ull s = redU[idx];
                add2(s, acc[bi][sp]);
                redU[idx] = s;
            }
    }
    __syncthreads();

    // all 256 threads: jj = t>>7, slot = t&127 -> b = (slot&31)*4 + (slot>>5)
    {
        int sj = t >> 7, slot = t & 127;
        int b = (slot & 31) * 4 + (slot >> 5);
        float res[16];
        #pragma unroll
        for (int sp = 0; sp < 8; sp++) {
            ull s = redU[sj*2048 + sp*128 + slot];
            add2(s, redU[sj*2048 + 1024 + sp*128 + slot]);
            upk2(res[2*sp], res[2*sp+1], s);
        }
        float4* dst = (float4*)&g_sp[(size_t)chunk * (BB*JS) + b * JS + (j0 + sj) * SS];
        #pragma unroll
        for (int q = 0; q < 4; q++)
            dst[q] = make_float4(res[q*4], res[q*4+1], res[q*4+2], res[q*4+3]);
    }
}

// ---------------- reduce partials + squash -> v ---------------------------------
__global__ void squash_k(float* __restrict__ out) {
    int b = blockIdx.x;      // 128
    int t = threadIdx.x;     // 512
    float sv = 0.0f;
    #pragma unroll 8
    for (int k = 0; k < NCHUNK; k++)
        sv += g_sp[(size_t)k * (BB*JS) + b * JS + t];

    __shared__ float sq[512];
    __shared__ float msqs[SS];
    sq[t] = sv * sv;
    __syncthreads();
    if (t < SS) {
        float m = 0.0f;
        #pragma unroll
        for (int jj = 0; jj < JJ; jj++) m += sq[jj * SS + t];
        msqs[t] = m;
    }
    __syncthreads();
    float msq = msqs[t & (SS - 1)];
    float scale = msq / ((1.0f + msq) * sqrtf(msq));
    out[b * JS + t] = sv * scale;
}

// ---------------- fused M-GEMM + b-update epilogue ------------------------------
#define MG_STAGE_F 10240   // floats per stage: As 32*256=8192 + Bs 32*64=2048
__global__ void __launch_bounds__(256, 2) mgemm_k(const float* __restrict__ x,
                                                  const float* __restrict__ v) {
    extern __shared__ __align__(16) float dsm[];
    int col0 = blockIdx.x * 64;    // 8
    int row0 = blockIdx.y * 256;   // 64  (one u: 256 | 2048)
    int t  = threadIdx.x;
    int tr = t >> 3;               // 0..31 -> rows tr*8..+8
    int tc = t & 7;                // 0..7  -> cols tc*8..+8

    unsigned smem_u32;
    { unsigned long long tmp = __cvta_generic_to_shared(dsm); smem_u32 = (unsigned)tmp; }

    ull acc[4][8];   // [row-pair][col]
    #pragma unroll
    for (int i = 0; i < 4; i++)
        #pragma unroll
        for (int q = 0; q < 8; q++) acc[i][q] = 0ULL;

    // issue stage 0
    {
        unsigned sb = smem_u32;
        #pragma unroll
        for (int i = 0; i < 8; i++) {
            int lin = i * 256 + t;            // A: 2048 float4
            int kk = lin >> 6, q = lin & 63;
            cpasync16(sb + kk * 1024 + q * 16, x + (size_t)kk * UC + row0 + q * 4);
        }
        #pragma unroll
        for (int i = 0; i < 2; i++) {
            int lin = i * 256 + t;            // B: 512 float4
            int kk = lin >> 4, q = lin & 15;
            cpasync16(sb + 32768 + kk * 256 + q * 16, v + (size_t)kk * JS + col0 + q * 4);
        }
        CP_COMMIT();
    }

    #pragma unroll 1
    for (int i = 0; i < 4; i++) {
        if (i < 3) {
            int k0n = (i + 1) * 32;
            unsigned sb = smem_u32 + ((i + 1) & 1) * (MG_STAGE_F * 4);
            #pragma unroll
            for (int q8 = 0; q8 < 8; q8++) {
                int lin = q8 * 256 + t;
                int kk = lin >> 6, q = lin & 63;
                cpasync16(sb + kk * 1024 + q * 16,
                          x + (size_t)(k0n + kk) * UC + row0 + q * 4);
            }
            #pragma unroll
            for (int q2 = 0; q2 < 2; q2++) {
                int lin = q2 * 256 + t;
                int kk = lin >> 4, q = lin & 15;
                cpasync16(sb + 32768 + kk * 256 + q * 16,
                          v + (size_t)(k0n + kk) * JS + col0 + q * 4);
            }
            CP_COMMIT();
            CP_WAIT(1);
        } else {
            CP_WAIT(0);
        }
        __syncthreads();

        const float* As = dsm + (i & 1) * MG_STAGE_F;
        const float* Bs = As + 32 * 256;
        #pragma unroll 8
        for (int kk = 0; kk < 32; kk++) {
            ulonglong2 ap0 = *(const ulonglong2*)&As[kk * 256 + tr * 8];
            ulonglong2 ap1 = *(const ulonglong2*)&As[kk * 256 + tr * 8 + 4];
            float4 b0 = *(const float4*)&Bs[kk * 64 + tc * 8];
            float4 b1 = *(const float4*)&Bs[kk * 64 + tc * 8 + 4];
            ull bd[8];
            bd[0] = pk2(b0.x, b0.x); bd[1] = pk2(b0.y, b0.y);
            bd[2] = pk2(b0.z, b0.z); bd[3] = pk2(b0.w, b0.w);
            bd[4] = pk2(b1.x, b1.x); bd[5] = pk2(b1.y, b1.y);
            bd[6] = pk2(b1.z, b1.z); bd[7] = pk2(b1.w, b1.w);
            ull ap[4] = {ap0.x, ap0.y, ap1.x, ap1.y};
            #pragma unroll
            for (int rp = 0; rp < 4; rp++)
                #pragma unroll
                for (int q = 0; q < 8; q++)
                    fma2(acc[rp][q], ap[rp], bd[q]);
        }
        __syncthreads();
    }

    // epilogue: thread cols = (one j, 8 s at s0); rows tr*8..+8 (pairs).
    int u  = row0 >> 11;
    int j  = (col0 >> 4) + (tc >> 1);
    int s0 = (tc & 1) * 8;
    #pragma unroll
    for (int rp = 0; rp < 4; rp++) {
        int clo = (row0 & 2047) + tr * 8 + rp * 2;
        float mlo[8], mhi[8];
        #pragma unroll
        for (int q = 0; q < 8; q++) upk2(mlo[q], mhi[q], acc[rp][q]);
        const float4* wlo = (const float4*)&g_Wr[(((size_t)clo * JJ + j) * UU + u) * SS + s0];
        const float4* whi = (const float4*)&g_Wr[(((size_t)(clo+1) * JJ + j) * UU + u) * SS + s0];
        float4 wl0 = wlo[0], wl1 = wlo[1];
        float4 wh0 = whi[0], wh1 = whi[1];
        float dlo = wl0.x*mlo[0] + wl0.y*mlo[1] + wl0.z*mlo[2] + wl0.w*mlo[3]
                  + wl1.x*mlo[4] + wl1.y*mlo[5] + wl1.z*mlo[6] + wl1.w*mlo[7];
        float dhi = wh0.x*mhi[0] + wh0.y*mhi[1] + wh0.z*mhi[2] + wh0.w*mhi[3]
                  + wh1.x*mhi[4] + wh1.y*mhi[5] + wh1.z*mhi[6] + wh1.w*mhi[7];
        float olo = __shfl_xor_sync(0xffffffffu, dlo, 1);
        float ohi = __shfl_xor_sync(0xffffffffu, dhi, 1);
        if ((tc & 1) == 0) {
            g_bp[((size_t)u * JJ + j) * CC + clo]     = dlo + olo;
            g_bp[((size_t)u * JJ + j) * CC + clo + 1] = dhi + ohi;
        }
    }
}

// ---------------- fused b-update reduce + softmax -------------------------------
__global__ void bsoftmax_k() {
    int j = blockIdx.x;       // 32
    int t = threadIdx.x;      // 512
    __shared__ float redm[16];
    __shared__ float reds[16];
    float4 bv = ((const float4*)(g_b + (size_t)j * CC))[t];
    float4 su = make_float4(0.f, 0.f, 0.f, 0.f);
    #pragma unroll
    for (int u = 0; u < UU; u++) {
        float4 p = ((const float4*)(g_bp + ((size_t)u * JJ + j) * CC))[t];
        su.x += p.x; su.y += p.y; su.z += p.z; su.w += p.w;
    }
    const float inv_b = 1.0f / (float)BB;
    bv.x += su.x * inv_b; bv.y += su.y * inv_b;
    bv.z += su.z * inv_b; bv.w += su.w * inv_b;
    ((float4*)(g_b + (size_t)j * CC))[t] = bv;

    float mx = fmaxf(fmaxf(bv.x, bv.y), fmaxf(bv.z, bv.w));
    #pragma unroll
    for (int o = 16; o > 0; o >>= 1) mx = fmaxf(mx, __shfl_xor_sync(0xffffffffu, mx, o));
    if ((t & 31) == 0) redm[t >> 5] = mx;
    __syncthreads();
    float bmax = redm[0];
    #pragma unroll
    for (int i = 1; i < 16; i++) bmax = fmaxf(bmax, redm[i]);
    float4 e;
    e.x = __expf(bv.x - bmax); e.y = __expf(bv.y - bmax);
    e.z = __expf(bv.z - bmax); e.w = __expf(bv.w - bmax);
    float sm = e.x + e.y + e.z + e.w;
    #pragma unroll
    for (int o = 16; o > 0; o >>= 1) sm += __shfl_xor_sync(0xffffffffu, sm, o);
    if ((t & 31) == 0) reds[t >> 5] = sm;
    __syncthreads();
    float tot = 0.0f;
    #pragma unroll
    for (int i = 0; i < 16; i++) tot += reds[i];
    float inv = 1.0f / tot;
    e.x *= inv; e.y *= inv; e.z *= inv; e.w *= inv;
    ((float4*)(g_c + (size_t)j * CC))[t] = e;
}

// ---------------- launcher --------------------------------------------------------
extern "C" void kernel_launch(void* const* d_in, const int* in_sizes, int n_in,
                              void* d_out, int out_size) {
    const float* x = (const float*)d_in[0];   // [B,U,C]
    const float* W = (const float*)d_in[1];   // [1,C,J,S,U]
    float* out = (float*)d_out;               // [B,J,S,1]

    cudaFuncSetAttribute(mgemm_k, cudaFuncAttributeMaxDynamicSharedMemorySize,
                         2 * MG_STAGE_F * 4);

    transpose_x_k<<<dim3(CC/32, BB/32, UU), dim3(32, 32)>>>(x);
    reorder_w_k<<<CC*JJ/2, 256>>>(W);
    init_k<<<(JJ*CC + 255)/256, 256>>>();

    for (int it = 0; it < NITER; it++) {
        s_pass_k<<<dim3(JJ/2, NCHUNK), 256>>>();
        squash_k<<<BB, 512>>>(out);
        if (it < NITER - 1) {
            mgemm_k<<<dim3(JS/64, UC/256), 256, 2 * MG_STAGE_F * 4>>>(x, out);
            bsoftmax_k<<<JJ, 512>>>();
        }
    }
}